// round 6
// baseline (speedup 1.0000x reference)
#include <cuda_runtime.h>
#include <cuda_fp16.h>
#include <math.h>

#define BB 64
#define FF 128
#define TT 1024
#define HH 512
#define GG 2048
#define NBLK 128

typedef unsigned long long ull;

// ---------------- device globals (no allocation allowed) ----------------
__device__ float   g_xTt[(size_t)TT * BB * FF];   // (T*B, F)
__device__ float   g_xg [(size_t)TT * BB * GG];   // (T*B, 4H) reused both layers
__device__ float   g_seq[(size_t)TT * BB * HH];   // layer0 h fp32 (T*B, H) for GEMM2
__device__ __half  g_h16[(size_t)TT * HH * BB];   // h fp16 [t][k][m]
__device__ __half  g_z16[HH * BB];                // zeros (never written)
__device__ unsigned g_flag[2][NBLK * 8];

// ---------------- helpers ----------------
__device__ __forceinline__ void fma2(ull& acc, ull a, ull b) {
    asm("fma.rn.f32x2 %0, %1, %2, %0;" : "+l"(acc) : "l"(a), "l"(b));
}
__device__ __forceinline__ ull dup2(float x) {
    ull r; asm("mov.b64 %0, {%1, %1};" : "=l"(r) : "f"(x)); return r;
}
__device__ __forceinline__ float2 unp(ull v) {
    float2 r; asm("mov.b64 {%0, %1}, %2;" : "=f"(r.x), "=f"(r.y) : "l"(v)); return r;
}
// half2 (as u32) -> packed f32x2 (ull); movs fold into register allocation
__device__ __forceinline__ ull h2w(unsigned h2) {
    ull r;
    asm("{\n\t.reg .f16 l, h;\n\t.reg .f32 fl, fh;\n\t"
        "mov.b32 {l, h}, %1;\n\t"
        "cvt.f32.f16 fl, l;\n\tcvt.f32.f16 fh, h;\n\t"
        "mov.b64 %0, {fl, fh};\n\t}" : "=l"(r) : "r"(h2));
    return r;
}
__device__ __forceinline__ float sigf(float x) { return 1.f / (1.f + __expf(-x)); }

__device__ __forceinline__ void st_release(unsigned* p, unsigned v) {
    asm volatile("st.release.gpu.global.u32 [%0], %1;" :: "l"(p), "r"(v) : "memory");
}
__device__ __forceinline__ unsigned ld_acquire(const unsigned* p) {
    unsigned v;
    asm volatile("ld.acquire.gpu.global.u32 %0, [%1];" : "=r"(v) : "l"(p) : "memory");
    return v;
}

// ---------------- reset flags ----------------
__global__ void reset_kernel() {
    for (int e = threadIdx.x; e < NBLK * 8; e += 256) { g_flag[0][e] = 0u; g_flag[1][e] = 0u; }
}

// ---------------- transpose x (B,F,T) -> (T*B, F) ----------------
__global__ void transpose_x_kernel(const float* __restrict__ x) {
    __shared__ float tile[32][33];
    int b  = blockIdx.z;
    int t0 = blockIdx.x * 32;
    int f0 = blockIdx.y * 32;
    for (int i = threadIdx.y; i < 32; i += 8)
        tile[i][threadIdx.x] = x[(size_t)b * FF * TT + (size_t)(f0 + i) * TT + t0 + threadIdx.x];
    __syncthreads();
    for (int i = threadIdx.y; i < 32; i += 8)
        g_xTt[((size_t)(t0 + i) * BB + b) * FF + f0 + threadIdx.x] = tile[threadIdx.x][i];
}

// ---------------- big GEMM: C(M,2048) = A(M,K) @ W(2048,K)^T + bih + bhh ----------------
template <int K>
__global__ __launch_bounds__(256, 2)
void gemm_gates(const float* __restrict__ A, const float* __restrict__ W,
                const float* __restrict__ bih, const float* __restrict__ bhh,
                float* __restrict__ C) {
    __shared__ __align__(16) float As[2][16][132];
    __shared__ __align__(16) float Bs[2][16][132];
    const int tid = threadIdx.x;
    const int m0 = blockIdx.y * 128, n0 = blockIdx.x * 128;
    const int srow = tid >> 1;
    const int sk0  = (tid & 1) * 8;

    const float* Ap = A + (size_t)(m0 + srow) * K + sk0;
    const float* Wp = W + (size_t)(n0 + srow) * K + sk0;
    float4 ra0 = *(const float4*)(Ap);
    float4 ra1 = *(const float4*)(Ap + 4);
    float4 rb0 = *(const float4*)(Wp);
    float4 rb1 = *(const float4*)(Wp + 4);

    const int mi = (tid >> 4) * 8;
    const int ni = (tid & 15) * 8;

    ull acc[8][4];
    #pragma unroll
    for (int n = 0; n < 8; ++n)
        #pragma unroll
        for (int p = 0; p < 4; ++p) acc[n][p] = 0ull;

    const int KT = K / 16;
    #pragma unroll 1
    for (int kt = 0; kt < KT; ++kt) {
        const int buf = kt & 1;
        #pragma unroll
        for (int c = 0; c < 4; ++c) {
            As[buf][sk0 + c][srow]     = ((const float*)&ra0)[c];
            As[buf][sk0 + 4 + c][srow] = ((const float*)&ra1)[c];
            Bs[buf][sk0 + c][srow]     = ((const float*)&rb0)[c];
            Bs[buf][sk0 + 4 + c][srow] = ((const float*)&rb1)[c];
        }
        if (kt + 1 < KT) {
            ra0 = *(const float4*)(Ap + (kt + 1) * 16);
            ra1 = *(const float4*)(Ap + (kt + 1) * 16 + 4);
            rb0 = *(const float4*)(Wp + (kt + 1) * 16);
            rb1 = *(const float4*)(Wp + (kt + 1) * 16 + 4);
        }
        __syncthreads();
        #pragma unroll
        for (int k = 0; k < 16; ++k) {
            ulonglong2 a0 = *(const ulonglong2*)&As[buf][k][mi];
            ulonglong2 a1 = *(const ulonglong2*)&As[buf][k][mi + 4];
            float4 b0 = *(const float4*)&Bs[buf][k][ni];
            float4 b1 = *(const float4*)&Bs[buf][k][ni + 4];
            ull am[4] = {a0.x, a0.y, a1.x, a1.y};
            float bs[8] = {b0.x, b0.y, b0.z, b0.w, b1.x, b1.y, b1.z, b1.w};
            #pragma unroll
            for (int n = 0; n < 8; ++n) {
                ull bb = dup2(bs[n]);
                fma2(acc[n][0], am[0], bb);
                fma2(acc[n][1], am[1], bb);
                fma2(acc[n][2], am[2], bb);
                fma2(acc[n][3], am[3], bb);
            }
        }
        __syncthreads();
    }

    float bn[8];
    #pragma unroll
    for (int u = 0; u < 8; ++u) bn[u] = bih[n0 + ni + u] + bhh[n0 + ni + u];

    #pragma unroll
    for (int p = 0; p < 4; ++p) {
        float2 v[8];
        #pragma unroll
        for (int n = 0; n < 8; ++n) v[n] = unp(acc[n][p]);
        size_t r0 = (size_t)(m0 + mi + 2 * p) * GG + n0 + ni;
        *(float4*)&C[r0]          = make_float4(v[0].x + bn[0], v[1].x + bn[1], v[2].x + bn[2], v[3].x + bn[3]);
        *(float4*)&C[r0 + 4]      = make_float4(v[4].x + bn[4], v[5].x + bn[5], v[6].x + bn[6], v[7].x + bn[7]);
        *(float4*)&C[r0 + GG]     = make_float4(v[0].y + bn[0], v[1].y + bn[1], v[2].y + bn[2], v[3].y + bn[3]);
        *(float4*)&C[r0 + GG + 4] = make_float4(v[4].y + bn[4], v[5].y + bn[5], v[6].y + bn[6], v[7].y + bn[7]);
    }
}

// ---------------- persistent LSTM recurrence (512 threads, 16 warps) ----------------
// 128 blocks, block owns h-cols [4blk, 4blk+4) (16 gate-cols). Warp w owns k-slice
// [32w, 32w+32). Lane = (j 0..3 col, mg 0..7 m-octet). h kept fp16 in SMEM (k-major),
// Whh pre-duplicated as f32x2 pairs in SMEM. Per k: 3 LDS.128 + 8 cvt + 16 fma2.
// Partials in SMEM -> reduce -> fused cell -> release/acquire grid barrier.
__global__ __launch_bounds__(512, 1)
void lstm_rec(const float* __restrict__ xg, const __half* __restrict__ z16,
              const float* __restrict__ Whh,
              float* __restrict__ seq, __half* __restrict__ h16,
              float* __restrict__ finalout, unsigned* __restrict__ flags) {
    extern __shared__ __align__(16) char smraw[];
    ull*    Ws2  = (ull*)smraw;                         // [512*16] dup f32x2, 64KB
    __half* Hs16 = (__half*)(smraw + 65536);            // [512][64] k-major,   64KB
    float*  part = (float*)(smraw + 131072);            // [16][64*17],       69.6KB
    float*  gred = (float*)(smraw + 131072 + 69632);    // [64*17],            4.3KB

    const int tid = threadIdx.x, blk = blockIdx.x;
    const int w = tid >> 5, lane = tid & 31;
    const int j = lane & 3, mg = lane >> 2;
    const int ks = w * 32;
    const int rowgrp = lane >> 3, c8 = lane & 7;        // staging map

    // stage Whh, duplicated: Ws2[k*16 + j*4 + q] = dup(Whh[(q*512 + blk*4 + j)*512 + k])
    for (int e = tid; e < 16 * 512; e += 512) {
        int g = e >> 9, k = e & 511;
        int jj = g >> 2, qq = g & 3;
        Ws2[k * 16 + jj * 4 + qq] = dup2(Whh[(size_t)(qq * HH + blk * 4 + jj) * HH + k]);
    }

    const int cm = tid & 63, cjj = (tid >> 6) & 3;      // cell map (tid<256)
    const int col = blk * 4 + cjj;
    const int r8 = tid >> 6;                            // reduce map (0..7)
    float creg = 0.f;
    __syncthreads();

    #pragma unroll 1
    for (int t = 0; t < TT; ++t) {
        const __half* hp = t ? (h16 + (size_t)(t - 1) * HH * BB) : z16;

        // cell threads fetch this step's precomputed input-gate terms early
        float x0 = 0.f, x1 = 0.f, x2 = 0.f, x3 = 0.f;
        if (tid < 256) {
            size_t xb = ((size_t)t * BB + cm) * GG + col;
            x0 = xg[xb]; x1 = xg[xb + 512]; x2 = xg[xb + 1024]; x3 = xg[xb + 1536];
        }

        ull acc[4][4];
        #pragma unroll
        for (int p = 0; p < 4; ++p)
            #pragma unroll
            for (int q = 0; q < 4; ++q) acc[p][q] = 0ull;

        // prefetch chunk 0 of own k-slice (16 rows x 128B)
        uint4 stg[4];
        #pragma unroll
        for (int i = 0; i < 4; ++i)
            stg[i] = *(const uint4*)(hp + (size_t)(ks + 4 * i + rowgrp) * BB + c8 * 8);

        #pragma unroll 1
        for (int c = 0; c < 2; ++c) {
            // store chunk c to Hs16
            #pragma unroll
            for (int i = 0; i < 4; ++i)
                *(uint4*)(Hs16 + (size_t)(ks + 16 * c + 4 * i + rowgrp) * BB + c8 * 8) = stg[i];
            __syncwarp();
            // prefetch chunk 1 (overlaps compute of chunk 0)
            if (c == 0) {
                #pragma unroll
                for (int i = 0; i < 4; ++i)
                    stg[i] = *(const uint4*)(hp + (size_t)(ks + 16 + 4 * i + rowgrp) * BB + c8 * 8);
            }
            // compute chunk c: 16 k; per k: 3 LDS.128 + 8 cvt + 16 fma2
            const __half* hbase = Hs16 + (size_t)(ks + 16 * c) * BB + mg * 8;
            const ull*    wbase = Ws2 + (ks + 16 * c) * 16 + j * 4;
            #pragma unroll
            for (int kk = 0; kk < 16; ++kk) {
                uint4 hv = *(const uint4*)(hbase + kk * BB);
                ulonglong2 w01 = *(const ulonglong2*)(wbase + kk * 16);
                ulonglong2 w23 = *(const ulonglong2*)(wbase + kk * 16 + 2);
                ull h0 = h2w(hv.x), h1 = h2w(hv.y), h2 = h2w(hv.z), h3 = h2w(hv.w);
                fma2(acc[0][0], h0, w01.x); fma2(acc[1][0], h1, w01.x);
                fma2(acc[2][0], h2, w01.x); fma2(acc[3][0], h3, w01.x);
                fma2(acc[0][1], h0, w01.y); fma2(acc[1][1], h1, w01.y);
                fma2(acc[2][1], h2, w01.y); fma2(acc[3][1], h3, w01.y);
                fma2(acc[0][2], h0, w23.x); fma2(acc[1][2], h1, w23.x);
                fma2(acc[2][2], h2, w23.x); fma2(acc[3][2], h3, w23.x);
                fma2(acc[0][3], h0, w23.y); fma2(acc[1][3], h1, w23.y);
                fma2(acc[2][3], h2, w23.y); fma2(acc[3][3], h3, w23.y);
            }
        }

        // write partials: acc[p][q] -> m pair (8mg+2p, 8mg+2p+1), gate j*4+q
        #pragma unroll
        for (int p = 0; p < 4; ++p) {
            int m0 = 8 * mg + 2 * p;
            #pragma unroll
            for (int q = 0; q < 4; ++q) {
                float2 s = unp(acc[p][q]);
                part[w * 1088 + m0 * 17 + j * 4 + q]       = s.x;
                part[w * 1088 + (m0 + 1) * 17 + j * 4 + q] = s.y;
            }
        }
        __syncthreads();

        // reduce over 16 warps: thread handles gates {r8, r8+8} for row cm
        {
            float s0 = 0.f, s1 = 0.f;
            #pragma unroll
            for (int ww = 0; ww < 16; ++ww) {
                const float* pp = part + ww * 1088 + cm * 17;
                s0 += pp[r8]; s1 += pp[r8 + 8];
            }
            gred[cm * 17 + r8]     = s0;
            gred[cm * 17 + r8 + 8] = s1;
        }
        __syncthreads();

        // fused cell (tid < 256)
        if (tid < 256) {
            const float* gp = gred + cm * 17 + cjj * 4;
            float gi_ = sigf (gp[0] + x0);
            float gf_ = sigf (gp[1] + x1);
            float gz_ = tanhf(gp[2] + x2);
            float go_ = sigf (gp[3] + x3);
            creg = gf_ * creg + gi_ * gz_;
            float h = go_ * tanhf(creg);

            if (seq) seq[((size_t)t * BB + cm) * HH + col] = h;
            h16[(size_t)t * HH * BB + (size_t)col * BB + cm] = __float2half(h);
            if (finalout && t == TT - 1) finalout[cm * HH + col] = h;
        }

        // grid barrier (release/acquire; no L1 flush)
        if (t < TT - 1) {
            __syncthreads();
            if (tid == 0) st_release(&flags[blk * 8], (unsigned)(t + 1));
            if (tid < NBLK) {
                while (ld_acquire(&flags[tid * 8]) < (unsigned)(t + 1)) __nanosleep(32);
            }
            __syncthreads();
        }
    }
}

// ---------------- launch ----------------
extern "C" void kernel_launch(void* const* d_in, const int* in_sizes, int n_in,
                              void* d_out, int out_size) {
    const float* x    = (const float*)d_in[0];
    const float* Wih0 = (const float*)d_in[1];
    const float* Whh0 = (const float*)d_in[2];
    const float* bih0 = (const float*)d_in[3];
    const float* bhh0 = (const float*)d_in[4];
    const float* Wih1 = (const float*)d_in[5];
    const float* Whh1 = (const float*)d_in[6];
    const float* bih1 = (const float*)d_in[7];
    const float* bhh1 = (const float*)d_in[8];
    float* out = (float*)d_out;

    float *xTt, *xg, *seq;
    __half *h16, *z16;
    unsigned* flags;
    cudaGetSymbolAddress((void**)&xTt,  g_xTt);
    cudaGetSymbolAddress((void**)&xg,   g_xg);
    cudaGetSymbolAddress((void**)&seq,  g_seq);
    cudaGetSymbolAddress((void**)&h16,  g_h16);
    cudaGetSymbolAddress((void**)&z16,  g_z16);
    cudaGetSymbolAddress((void**)&flags, g_flag);

    const int smem = 65536 + 65536 + 69632 + 17 * 64 * 4;  // Ws2 + Hs16 + part + gred
    cudaFuncSetAttribute(lstm_rec, cudaFuncAttributeMaxDynamicSharedMemorySize, smem);

    reset_kernel<<<1, 256>>>();

    dim3 tb(32, 8), tg(TT / 32, FF / 32, BB);
    transpose_x_kernel<<<tg, tb>>>(x);

    gemm_gates<FF><<<dim3(GG / 128, TT * BB / 128), 256>>>(xTt, Wih0, bih0, bhh0, xg);
    lstm_rec<<<NBLK, 512, smem>>>(xg, z16, Whh0, seq, h16, nullptr, flags);
    gemm_gates<HH><<<dim3(GG / 128, TT * BB / 128), 256>>>(seq, Wih1, bih1, bhh1, xg);
    lstm_rec<<<NBLK, 512, smem>>>(xg, z16, Whh1, nullptr, h16, out, flags + NBLK * 8);
}

// round 9
// speedup vs baseline: 1.7218x; 1.7218x over previous
#include <cuda_runtime.h>
#include <cuda_fp16.h>
#include <math.h>

#define BB 64
#define FF 128
#define TT 1024
#define HH 512
#define GG 2048
#define NBLK 128

typedef unsigned long long ull;
typedef unsigned int u32;

// ---------------- device globals (no allocation allowed) ----------------
__device__ float   g_xTt[(size_t)TT * BB * FF];   // (T*B, F)
__device__ float   g_xg [(size_t)TT * BB * GG];   // [t*64+m][blk*16 + q*4 + j]
__device__ float   g_seq[(size_t)TT * BB * HH];   // layer0 h fp32 for GEMM2
__device__ __half  g_h16[(size_t)TT * BB * HH];   // h fp16 [t][m][k]
__device__ u32     g_flag[2][NBLK * 8];

// ---------------- helpers ----------------
__device__ __forceinline__ void fma2(ull& acc, ull a, ull b) {
    asm("fma.rn.f32x2 %0, %1, %2, %0;" : "+l"(acc) : "l"(a), "l"(b));
}
__device__ __forceinline__ ull dup2(float x) {
    ull r; asm("mov.b64 %0, {%1, %1};" : "=l"(r) : "f"(x)); return r;
}
__device__ __forceinline__ float2 unp(ull v) {
    float2 r; asm("mov.b64 {%0, %1}, %2;" : "=f"(r.x), "=f"(r.y) : "l"(v)); return r;
}
__device__ __forceinline__ float sigf(float x) { return 1.f / (1.f + __expf(-x)); }

__device__ __forceinline__ void st_release(u32* p, u32 v) {
    asm volatile("st.release.gpu.global.u32 [%0], %1;" :: "l"(p), "r"(v) : "memory");
}
__device__ __forceinline__ u32 ld_acquire(const u32* p) {
    u32 v;
    asm volatile("ld.acquire.gpu.global.u32 %0, [%1];" : "=r"(v) : "l"(p) : "memory");
    return v;
}
__device__ __forceinline__ u32 smem_u32(const void* p) {
    u32 a;
    asm("{ .reg .u64 t; cvta.to.shared.u64 t, %1; cvt.u32.u64 %0, t; }" : "=r"(a) : "l"(p));
    return a;
}

__device__ __forceinline__ void ldsm_x4(u32& r0, u32& r1, u32& r2, u32& r3, u32 addr) {
    asm volatile("ldmatrix.sync.aligned.m8n8.x4.shared.b16 {%0,%1,%2,%3}, [%4];"
                 : "=r"(r0), "=r"(r1), "=r"(r2), "=r"(r3) : "r"(addr));
}
__device__ __forceinline__ void ldsm_x2(u32& r0, u32& r1, u32 addr) {
    asm volatile("ldmatrix.sync.aligned.m8n8.x2.shared.b16 {%0,%1}, [%2];"
                 : "=r"(r0), "=r"(r1) : "r"(addr));
}
__device__ __forceinline__ void mma16816(float& c0, float& c1, float& c2, float& c3,
                                         u32 a0, u32 a1, u32 a2, u32 a3, u32 b0, u32 b1) {
    asm volatile("mma.sync.aligned.m16n8k16.row.col.f32.f16.f16.f32 "
                 "{%0,%1,%2,%3}, {%4,%5,%6,%7}, {%8,%9}, {%0,%1,%2,%3};"
                 : "+f"(c0), "+f"(c1), "+f"(c2), "+f"(c3)
                 : "r"(a0), "r"(a1), "r"(a2), "r"(a3), "r"(b0), "r"(b1));
}

// ---------------- reset flags ----------------
__global__ void reset_kernel() {
    for (int e = threadIdx.x; e < NBLK * 8; e += 256) { g_flag[0][e] = 0u; g_flag[1][e] = 0u; }
}

// ---------------- transpose x (B,F,T) -> (T*B, F) ----------------
__global__ void transpose_x_kernel(const float* __restrict__ x) {
    __shared__ float tile[32][33];
    int b  = blockIdx.z;
    int t0 = blockIdx.x * 32;
    int f0 = blockIdx.y * 32;
    for (int i = threadIdx.y; i < 32; i += 8)
        tile[i][threadIdx.x] = x[(size_t)b * FF * TT + (size_t)(f0 + i) * TT + t0 + threadIdx.x];
    __syncthreads();
    for (int i = threadIdx.y; i < 32; i += 8)
        g_xTt[((size_t)(t0 + i) * BB + b) * FF + f0 + threadIdx.x] = tile[threadIdx.x][i];
}

// ---------------- big GEMM: gates = A(M,K) @ W(2048,K)^T + bih + bhh ----------------
// Output layout: C[row][(hcol>>2)*16 + q*4 + (hcol&3)] where gate n = q*512 + hcol.
template <int K>
__global__ __launch_bounds__(256, 2)
void gemm_gates(const float* __restrict__ A, const float* __restrict__ W,
                const float* __restrict__ bih, const float* __restrict__ bhh,
                float* __restrict__ C) {
    __shared__ __align__(16) float As[2][16][132];
    __shared__ __align__(16) float Bs[2][16][132];
    const int tid = threadIdx.x;
    const int m0 = blockIdx.y * 128, n0 = blockIdx.x * 128;
    const int srow = tid >> 1;
    const int sk0  = (tid & 1) * 8;

    const float* Ap = A + (size_t)(m0 + srow) * K + sk0;
    const float* Wp = W + (size_t)(n0 + srow) * K + sk0;
    float4 ra0 = *(const float4*)(Ap);
    float4 ra1 = *(const float4*)(Ap + 4);
    float4 rb0 = *(const float4*)(Wp);
    float4 rb1 = *(const float4*)(Wp + 4);

    const int mi = (tid >> 4) * 8;
    const int ni = (tid & 15) * 8;

    ull acc[8][4];
    #pragma unroll
    for (int n = 0; n < 8; ++n)
        #pragma unroll
        for (int p = 0; p < 4; ++p) acc[n][p] = 0ull;

    const int KT = K / 16;
    #pragma unroll 1
    for (int kt = 0; kt < KT; ++kt) {
        const int buf = kt & 1;
        #pragma unroll
        for (int c = 0; c < 4; ++c) {
            As[buf][sk0 + c][srow]     = ((const float*)&ra0)[c];
            As[buf][sk0 + 4 + c][srow] = ((const float*)&ra1)[c];
            Bs[buf][sk0 + c][srow]     = ((const float*)&rb0)[c];
            Bs[buf][sk0 + 4 + c][srow] = ((const float*)&rb1)[c];
        }
        if (kt + 1 < KT) {
            ra0 = *(const float4*)(Ap + (kt + 1) * 16);
            ra1 = *(const float4*)(Ap + (kt + 1) * 16 + 4);
            rb0 = *(const float4*)(Wp + (kt + 1) * 16);
            rb1 = *(const float4*)(Wp + (kt + 1) * 16 + 4);
        }
        __syncthreads();
        #pragma unroll
        for (int k = 0; k < 16; ++k) {
            ulonglong2 a0 = *(const ulonglong2*)&As[buf][k][mi];
            ulonglong2 a1 = *(const ulonglong2*)&As[buf][k][mi + 4];
            float4 b0 = *(const float4*)&Bs[buf][k][ni];
            float4 b1 = *(const float4*)&Bs[buf][k][ni + 4];
            ull am[4] = {a0.x, a0.y, a1.x, a1.y};
            float bs[8] = {b0.x, b0.y, b0.z, b0.w, b1.x, b1.y, b1.z, b1.w};
            #pragma unroll
            for (int n = 0; n < 8; ++n) {
                ull bb = dup2(bs[n]);
                fma2(acc[n][0], am[0], bb);
                fma2(acc[n][1], am[1], bb);
                fma2(acc[n][2], am[2], bb);
                fma2(acc[n][3], am[3], bb);
            }
        }
        __syncthreads();
    }

    float bn[8];
    #pragma unroll
    for (int u = 0; u < 8; ++u) bn[u] = bih[n0 + ni + u] + bhh[n0 + ni + u];

    const int ng = n0 + ni;
    const int q  = ng >> 9;
    const int hc = ng & 511;
    const size_t cb = (size_t)((hc >> 2) << 4) + q * 4;

    #pragma unroll
    for (int p = 0; p < 4; ++p) {
        float2 v[8];
        #pragma unroll
        for (int n = 0; n < 8; ++n) v[n] = unp(acc[n][p]);
        size_t r0 = (size_t)(m0 + mi + 2 * p) * GG + cb;
        size_t r1 = r0 + GG;
        *(float4*)&C[r0]      = make_float4(v[0].x + bn[0], v[1].x + bn[1], v[2].x + bn[2], v[3].x + bn[3]);
        *(float4*)&C[r0 + 16] = make_float4(v[4].x + bn[4], v[5].x + bn[5], v[6].x + bn[6], v[7].x + bn[7]);
        *(float4*)&C[r1]      = make_float4(v[0].y + bn[0], v[1].y + bn[1], v[2].y + bn[2], v[3].y + bn[3]);
        *(float4*)&C[r1 + 16] = make_float4(v[4].y + bn[4], v[5].y + bn[5], v[6].y + bn[6], v[7].y + bn[7]);
    }
}

// ---------------- persistent HMMA LSTM recurrence ----------------
// 128 blocks, 256 threads (8 warps). Block owns h-cols [4blk,4blk+4) = 16 gate-cols.
// Warp wid -> (mt = wid&3, nt = wid>>2): C tile m16 x n8 over K=512 (32 k-tiles of
// mma.m16n8k16). Whh fragments in registers (loaded once). h staged to SMEM with
// XOR-8 chunk swizzle; per k-tile: 1 ldmatrix.x4 (A) + 1 mma. Gates via SMEM, fused
// cell, release/acquire flag grid barrier.
#define HS_OFF   0
#define BS_OFF   65536
#define GT_OFF   (65536 + 16384)
#define SMEM_TOTAL (65536 + 16384 + 64 * 18 * 4)

__global__ __launch_bounds__(256, 1)
void lstm_rec(const float* __restrict__ xg, const float* __restrict__ Whh,
              float* __restrict__ seq, __half* __restrict__ h16,
              float* __restrict__ finalout, u32* __restrict__ flags) {
    extern __shared__ __align__(16) char smraw[];
    const u32 hs_base = smem_u32(smraw + HS_OFF);
    const u32 bs_base = smem_u32(smraw + BS_OFF);
    float* gates = (float*)(smraw + GT_OFF);          // [64][18]

    const int tid = threadIdx.x, blk = blockIdx.x;
    const int wid = tid >> 5, lane = tid & 31;
    const int mt = wid & 3, nt = wid >> 2;

    // ---- stage Whh slice (16 x 512 f16, swizzled) ----
    for (int e = tid; e < 1024; e += 256) {           // 16 rows x 64 chunks
        int row = e >> 6, c = e & 63;
        const float* wsrc = Whh + (size_t)((row >> 2) * HH + blk * 4 + (row & 3)) * HH + c * 8;
        float4 f0 = *(const float4*)wsrc;
        float4 f1 = *(const float4*)(wsrc + 4);
        __half2 h0 = __floats2half2_rn(f0.x, f0.y);
        __half2 h1 = __floats2half2_rn(f0.z, f0.w);
        __half2 h2 = __floats2half2_rn(f1.x, f1.y);
        __half2 h3 = __floats2half2_rn(f1.z, f1.w);
        u32 off = row * 1024 + ((u32)(c ^ (row & 7))) * 16;
        *(uint4*)(smraw + BS_OFF + off) = make_uint4(*(u32*)&h0, *(u32*)&h1, *(u32*)&h2, *(u32*)&h3);
    }
    __syncthreads();

    // ---- load B fragments to registers (once): 32 k-tiles x {b0,b1} ----
    u32 bf0[32], bf1[32];
    {
        int al = lane & 15;
        int brow = nt * 8 + (al & 7);
        int tsel = (al >> 3) & 1;
        u32 baddr_base = bs_base + brow * 1024;
        int bs = brow & 7;
        #pragma unroll
        for (int kt = 0; kt < 32; ++kt) {
            u32 ch = (u32)((2 * kt + tsel) ^ bs);
            ldsm_x2(bf0[kt], bf1[kt], baddr_base + ch * 16);
        }
    }

    // A ldmatrix lane mapping (per step, per k-tile)
    const int arow = mt * 16 + ((lane >> 3) & 1) * 8 + (lane & 7);
    const int at16 = (lane >> 4) & 1;
    const int as   = arow & 7;
    const u32 a_lane_base = hs_base + arow * 1024;

    // cell mapping: thread = (m, j)
    const int cm = tid >> 2, cj = tid & 3;
    const int col = blk * 4 + cj;
    float creg = 0.f;

    // C fragment coords for epilogue
    const int crow = mt * 16 + (lane >> 2);
    const int ccol = nt * 8 + 2 * (lane & 3);

    #pragma unroll 1
    for (int t = 0; t < TT; ++t) {
        // prefetch xg early (4 scalars, stride 4)
        const float* xp = xg + ((size_t)t * BB + cm) * GG + blk * 16 + cj;
        float x0 = xp[0], x1 = xp[4], x2 = xp[8], x3 = xp[12];

        // ---- stage h[t-1] (64 x 512 f16) into Hs, swizzled ----
        if (t == 0) {
            for (int i = 0; i < 16; ++i) {
                int e = i * 256 + tid;
                int row = e >> 6, c = e & 63;
                u32 off = row * 1024 + ((u32)(c ^ (row & 7))) * 16;
                *(uint4*)(smraw + HS_OFF + off) = make_uint4(0u, 0u, 0u, 0u);
            }
        } else {
            const __half* hp = h16 + (size_t)(t - 1) * BB * HH;
            #pragma unroll
            for (int i = 0; i < 16; ++i) {
                int e = i * 256 + tid;
                int row = e >> 6, c = e & 63;
                uint4 v = *(const uint4*)(hp + (size_t)row * HH + c * 8);
                u32 off = row * 1024 + ((u32)(c ^ (row & 7))) * 16;
                *(uint4*)(smraw + HS_OFF + off) = v;
            }
        }
        __syncthreads();

        // ---- MMA: 32 k-tiles ----
        float c0 = 0.f, c1 = 0.f, c2 = 0.f, c3 = 0.f;
        #pragma unroll
        for (int kt = 0; kt < 32; ++kt) {
            u32 ch = (u32)((2 * kt + at16) ^ as);
            u32 a0, a1, a2, a3;
            ldsm_x4(a0, a1, a2, a3, a_lane_base + ch * 16);
            mma16816(c0, c1, c2, c3, a0, a1, a2, a3, bf0[kt], bf1[kt]);
        }

        // ---- epilogue: C frags -> gates SMEM ----
        *(float2*)&gates[crow * 18 + ccol]       = make_float2(c0, c1);
        *(float2*)&gates[(crow + 8) * 18 + ccol] = make_float2(c2, c3);
        __syncthreads();

        // ---- fused cell: thread (m, j) ----
        {
            const float* gp = gates + cm * 18 + cj;
            float gi_ = sigf (gp[0]  + x0);
            float gf_ = sigf (gp[4]  + x1);
            float gz_ = tanhf(gp[8]  + x2);
            float go_ = sigf (gp[12] + x3);
            creg = gf_ * creg + gi_ * gz_;
            float h = go_ * tanhf(creg);

            size_t ho = ((size_t)t * BB + cm) * HH + col;
            h16[ho] = __float2half(h);
            if (seq) seq[ho] = h;
            if (finalout && t == TT - 1) finalout[(size_t)cm * HH + col] = h;
        }

        // ---- grid barrier ----
        if (t < TT - 1) {
            __syncthreads();
            if (tid == 0) st_release(&flags[blk * 8], (u32)(t + 1));
            if (tid < NBLK) {
                while (ld_acquire(&flags[tid * 8]) < (u32)(t + 1)) __nanosleep(32);
            }
            __syncthreads();
        }
    }
}

// ---------------- launch ----------------
extern "C" void kernel_launch(void* const* d_in, const int* in_sizes, int n_in,
                              void* d_out, int out_size) {
    const float* x    = (const float*)d_in[0];
    const float* Wih0 = (const float*)d_in[1];
    const float* Whh0 = (const float*)d_in[2];
    const float* bih0 = (const float*)d_in[3];
    const float* bhh0 = (const float*)d_in[4];
    const float* Wih1 = (const float*)d_in[5];
    const float* Whh1 = (const float*)d_in[6];
    const float* bih1 = (const float*)d_in[7];
    const float* bhh1 = (const float*)d_in[8];
    float* out = (float*)d_out;

    float *xTt, *xg, *seq;
    __half* h16;
    u32* flags;
    cudaGetSymbolAddress((void**)&xTt,  g_xTt);
    cudaGetSymbolAddress((void**)&xg,   g_xg);
    cudaGetSymbolAddress((void**)&seq,  g_seq);
    cudaGetSymbolAddress((void**)&h16,  g_h16);
    cudaGetSymbolAddress((void**)&flags, g_flag);

    cudaFuncSetAttribute(lstm_rec, cudaFuncAttributeMaxDynamicSharedMemorySize, SMEM_TOTAL);

    reset_kernel<<<1, 256>>>();

    dim3 tb(32, 8), tg(TT / 32, FF / 32, BB);
    transpose_x_kernel<<<tg, tb>>>(x);

    gemm_gates<FF><<<dim3(GG / 128, TT * BB / 128), 256>>>(xTt, Wih0, bih0, bhh0, xg);
    lstm_rec<<<NBLK, 256, SMEM_TOTAL>>>(xg, Whh0, seq, h16, nullptr, flags);
    gemm_gates<HH><<<dim3(GG / 128, TT * BB / 128), 256>>>(seq, Wih1, bih1, bhh1, xg);
    lstm_rec<<<NBLK, 256, SMEM_TOTAL>>>(xg, Whh1, nullptr, h16, out, flags + NBLK * 8);
}

// round 10
// speedup vs baseline: 2.3757x; 1.3798x over previous
#include <cuda_runtime.h>
#include <cuda_fp16.h>
#include <math.h>

#define BB 64
#define FF 128
#define TT 1024
#define HH 512
#define GG 2048
#define NBLK 128

typedef unsigned long long ull;
typedef unsigned int u32;

// ---------------- device globals (no allocation allowed) ----------------
__device__ float   g_xTt [(size_t)TT * BB * FF];   // (T*B, F)
__device__ float   g_xg  [(size_t)TT * BB * GG];   // layer0 gate preacts (permuted layout)
__device__ __half  g_h016[(size_t)TT * BB * HH];   // layer0 h f16 [t][m][k]
__device__ __half  g_h116[(size_t)TT * BB * HH];   // layer1 h f16 [s][m][k]
__device__ u32     g_flag[NBLK * 8];

// ---------------- helpers ----------------
__device__ __forceinline__ void fma2(ull& acc, ull a, ull b) {
    asm("fma.rn.f32x2 %0, %1, %2, %0;" : "+l"(acc) : "l"(a), "l"(b));
}
__device__ __forceinline__ ull dup2(float x) {
    ull r; asm("mov.b64 %0, {%1, %1};" : "=l"(r) : "f"(x)); return r;
}
__device__ __forceinline__ float2 unp(ull v) {
    float2 r; asm("mov.b64 {%0, %1}, %2;" : "=f"(r.x), "=f"(r.y) : "l"(v)); return r;
}
__device__ __forceinline__ float sigf(float x) { return 1.f / (1.f + __expf(-x)); }

__device__ __forceinline__ void st_release(u32* p, u32 v) {
    asm volatile("st.release.gpu.global.u32 [%0], %1;" :: "l"(p), "r"(v) : "memory");
}
__device__ __forceinline__ u32 ld_acquire(const u32* p) {
    u32 v;
    asm volatile("ld.acquire.gpu.global.u32 %0, [%1];" : "=r"(v) : "l"(p) : "memory");
    return v;
}
__device__ __forceinline__ u32 smem_u32(const void* p) {
    u32 a;
    asm("{ .reg .u64 t; cvta.to.shared.u64 t, %1; cvt.u32.u64 %0, t; }" : "=r"(a) : "l"(p));
    return a;
}

__device__ __forceinline__ void ldsm_x4(u32& r0, u32& r1, u32& r2, u32& r3, u32 addr) {
    asm volatile("ldmatrix.sync.aligned.m8n8.x4.shared.b16 {%0,%1,%2,%3}, [%4];"
                 : "=r"(r0), "=r"(r1), "=r"(r2), "=r"(r3) : "r"(addr));
}
__device__ __forceinline__ void ldsm_x2(u32& r0, u32& r1, u32 addr) {
    asm volatile("ldmatrix.sync.aligned.m8n8.x2.shared.b16 {%0,%1}, [%2];"
                 : "=r"(r0), "=r"(r1) : "r"(addr));
}
__device__ __forceinline__ void mma16816(float& c0, float& c1, float& c2, float& c3,
                                         u32 a0, u32 a1, u32 a2, u32 a3, u32 b0, u32 b1) {
    asm volatile("mma.sync.aligned.m16n8k16.row.col.f32.f16.f16.f32 "
                 "{%0,%1,%2,%3}, {%4,%5,%6,%7}, {%8,%9}, {%0,%1,%2,%3};"
                 : "+f"(c0), "+f"(c1), "+f"(c2), "+f"(c3)
                 : "r"(a0), "r"(a1), "r"(a2), "r"(a3), "r"(b0), "r"(b1));
}

// ---------------- reset flags ----------------
__global__ void reset_kernel() {
    for (int e = threadIdx.x; e < NBLK * 8; e += 256) g_flag[e] = 0u;
}

// ---------------- transpose x (B,F,T) -> (T*B, F) ----------------
__global__ void transpose_x_kernel(const float* __restrict__ x) {
    __shared__ float tile[32][33];
    int b  = blockIdx.z;
    int t0 = blockIdx.x * 32;
    int f0 = blockIdx.y * 32;
    for (int i = threadIdx.y; i < 32; i += 8)
        tile[i][threadIdx.x] = x[(size_t)b * FF * TT + (size_t)(f0 + i) * TT + t0 + threadIdx.x];
    __syncthreads();
    for (int i = threadIdx.y; i < 32; i += 8)
        g_xTt[((size_t)(t0 + i) * BB + b) * FF + f0 + threadIdx.x] = tile[threadIdx.x][i];
}

// ---------------- layer0 input GEMM: xg = xTt(M,128) @ Wih0^T + bih0 + bhh0 ----------------
// Output layout: C[row][(hcol>>2)*16 + q*4 + (hcol&3)], gate n = q*512 + hcol.
template <int K>
__global__ __launch_bounds__(256, 2)
void gemm_gates(const float* __restrict__ A, const float* __restrict__ W,
                const float* __restrict__ bih, const float* __restrict__ bhh,
                float* __restrict__ C) {
    __shared__ __align__(16) float As[2][16][132];
    __shared__ __align__(16) float Bs[2][16][132];
    const int tid = threadIdx.x;
    const int m0 = blockIdx.y * 128, n0 = blockIdx.x * 128;
    const int srow = tid >> 1;
    const int sk0  = (tid & 1) * 8;

    const float* Ap = A + (size_t)(m0 + srow) * K + sk0;
    const float* Wp = W + (size_t)(n0 + srow) * K + sk0;
    float4 ra0 = *(const float4*)(Ap);
    float4 ra1 = *(const float4*)(Ap + 4);
    float4 rb0 = *(const float4*)(Wp);
    float4 rb1 = *(const float4*)(Wp + 4);

    const int mi = (tid >> 4) * 8;
    const int ni = (tid & 15) * 8;

    ull acc[8][4];
    #pragma unroll
    for (int n = 0; n < 8; ++n)
        #pragma unroll
        for (int p = 0; p < 4; ++p) acc[n][p] = 0ull;

    const int KT = K / 16;
    #pragma unroll 1
    for (int kt = 0; kt < KT; ++kt) {
        const int buf = kt & 1;
        #pragma unroll
        for (int c = 0; c < 4; ++c) {
            As[buf][sk0 + c][srow]     = ((const float*)&ra0)[c];
            As[buf][sk0 + 4 + c][srow] = ((const float*)&ra1)[c];
            Bs[buf][sk0 + c][srow]     = ((const float*)&rb0)[c];
            Bs[buf][sk0 + 4 + c][srow] = ((const float*)&rb1)[c];
        }
        if (kt + 1 < KT) {
            ra0 = *(const float4*)(Ap + (kt + 1) * 16);
            ra1 = *(const float4*)(Ap + (kt + 1) * 16 + 4);
            rb0 = *(const float4*)(Wp + (kt + 1) * 16);
            rb1 = *(const float4*)(Wp + (kt + 1) * 16 + 4);
        }
        __syncthreads();
        #pragma unroll
        for (int k = 0; k < 16; ++k) {
            ulonglong2 a0 = *(const ulonglong2*)&As[buf][k][mi];
            ulonglong2 a1 = *(const ulonglong2*)&As[buf][k][mi + 4];
            float4 b0 = *(const float4*)&Bs[buf][k][ni];
            float4 b1 = *(const float4*)&Bs[buf][k][ni + 4];
            ull am[4] = {a0.x, a0.y, a1.x, a1.y};
            float bs[8] = {b0.x, b0.y, b0.z, b0.w, b1.x, b1.y, b1.z, b1.w};
            #pragma unroll
            for (int n = 0; n < 8; ++n) {
                ull bb = dup2(bs[n]);
                fma2(acc[n][0], am[0], bb);
                fma2(acc[n][1], am[1], bb);
                fma2(acc[n][2], am[2], bb);
                fma2(acc[n][3], am[3], bb);
            }
        }
        __syncthreads();
    }

    float bn[8];
    #pragma unroll
    for (int u = 0; u < 8; ++u) bn[u] = bih[n0 + ni + u] + bhh[n0 + ni + u];

    const int ng = n0 + ni;
    const int q  = ng >> 9;
    const int hc = ng & 511;
    const size_t cb = (size_t)((hc >> 2) << 4) + q * 4;

    #pragma unroll
    for (int p = 0; p < 4; ++p) {
        float2 v[8];
        #pragma unroll
        for (int n = 0; n < 8; ++n) v[n] = unp(acc[n][p]);
        size_t r0 = (size_t)(m0 + mi + 2 * p) * GG + cb;
        size_t r1 = r0 + GG;
        *(float4*)&C[r0]      = make_float4(v[0].x + bn[0], v[1].x + bn[1], v[2].x + bn[2], v[3].x + bn[3]);
        *(float4*)&C[r0 + 16] = make_float4(v[4].x + bn[4], v[5].x + bn[5], v[6].x + bn[6], v[7].x + bn[7]);
        *(float4*)&C[r1]      = make_float4(v[0].y + bn[0], v[1].y + bn[1], v[2].y + bn[2], v[3].y + bn[3]);
        *(float4*)&C[r1 + 16] = make_float4(v[4].y + bn[4], v[5].y + bn[5], v[6].y + bn[6], v[7].y + bn[7]);
    }
}

// ---------------- fused 2-layer persistent HMMA LSTM (1-step skew) ----------------
// Iteration i: layer0 computes h0[i] (i<TT); layer1 computes h1[i-1] (i>=1), with
//   gates1 = h1[i-2] @ Whh1_slice^T + h0[i-1] @ Wih1_slice^T + b1.
// h0[i-1] staged in Hs0 serves BOTH layer0's recurrence and layer1's input half.
#define HS0_OFF  0
#define HS1_OFF  65536
#define B0_OFF   131072
#define B1A_OFF  (131072 + 16384)
#define B1B_OFF  (131072 + 32768)
#define GT0_OFF  (131072 + 49152)
#define GT1_OFF  (GT0_OFF + 4608)
#define SMEM_TOTAL (GT1_OFF + 4608)

__global__ __launch_bounds__(256, 1)
void lstm_fused(const float* __restrict__ xg,
                const float* __restrict__ Whh0,
                const float* __restrict__ Whh1, const float* __restrict__ Wih1,
                const float* __restrict__ bih1, const float* __restrict__ bhh1,
                __half* __restrict__ h016, __half* __restrict__ h116,
                float* __restrict__ finalout, u32* __restrict__ flags) {
    extern __shared__ __align__(16) char smraw[];
    const u32 hs0_base = smem_u32(smraw + HS0_OFF);
    const u32 hs1_base = smem_u32(smraw + HS1_OFF);
    const u32 b0_base  = smem_u32(smraw + B0_OFF);
    const u32 b1a_base = smem_u32(smraw + B1A_OFF);
    const u32 b1b_base = smem_u32(smraw + B1B_OFF);
    float* gates0 = (float*)(smraw + GT0_OFF);      // [64][18]
    float* gates1 = (float*)(smraw + GT1_OFF);      // [64][18]

    const int tid = threadIdx.x, blk = blockIdx.x;
    const int wid = tid >> 5, lane = tid & 31;
    const int mt = wid & 3, nt = wid >> 2;

    // ---- stage the three weight slices (16 x 512 f16 each, swizzled), once ----
    for (int e = tid; e < 1024; e += 256) {
        int row = e >> 6, c = e & 63;
        size_t wr = (size_t)((row >> 2) * HH + blk * 4 + (row & 3)) * HH + c * 8;
        u32 off = row * 1024 + ((u32)(c ^ (row & 7))) * 16;
        {
            float4 f0 = *(const float4*)(Whh0 + wr);
            float4 f1 = *(const float4*)(Whh0 + wr + 4);
            __half2 h0 = __floats2half2_rn(f0.x, f0.y), h1 = __floats2half2_rn(f0.z, f0.w);
            __half2 h2 = __floats2half2_rn(f1.x, f1.y), h3 = __floats2half2_rn(f1.z, f1.w);
            *(uint4*)(smraw + B0_OFF + off) = make_uint4(*(u32*)&h0, *(u32*)&h1, *(u32*)&h2, *(u32*)&h3);
        }
        {
            float4 f0 = *(const float4*)(Whh1 + wr);
            float4 f1 = *(const float4*)(Whh1 + wr + 4);
            __half2 h0 = __floats2half2_rn(f0.x, f0.y), h1 = __floats2half2_rn(f0.z, f0.w);
            __half2 h2 = __floats2half2_rn(f1.x, f1.y), h3 = __floats2half2_rn(f1.z, f1.w);
            *(uint4*)(smraw + B1A_OFF + off) = make_uint4(*(u32*)&h0, *(u32*)&h1, *(u32*)&h2, *(u32*)&h3);
        }
        {
            float4 f0 = *(const float4*)(Wih1 + wr);
            float4 f1 = *(const float4*)(Wih1 + wr + 4);
            __half2 h0 = __floats2half2_rn(f0.x, f0.y), h1 = __floats2half2_rn(f0.z, f0.w);
            __half2 h2 = __floats2half2_rn(f1.x, f1.y), h3 = __floats2half2_rn(f1.z, f1.w);
            *(uint4*)(smraw + B1B_OFF + off) = make_uint4(*(u32*)&h0, *(u32*)&h1, *(u32*)&h2, *(u32*)&h3);
        }
    }
    __syncthreads();

    // ---- layer0 B fragments to registers (once): 32 ktiles x {b0,b1} ----
    u32 bf0[32], bf1[32];
    const int al = lane & 15;
    const int brow = nt * 8 + (al & 7);
    const int btsel = (al >> 3) & 1;
    const int bsw = brow & 7;
    {
        u32 bbase = b0_base + brow * 1024;
        #pragma unroll
        for (int kt = 0; kt < 32; ++kt) {
            u32 ch = (u32)((2 * kt + btsel) ^ bsw);
            ldsm_x2(bf0[kt], bf1[kt], bbase + ch * 16);
        }
    }
    const u32 b1a_lane = b1a_base + brow * 1024;
    const u32 b1b_lane = b1b_base + brow * 1024;

    // A ldmatrix lane mapping
    const int arow = mt * 16 + ((lane >> 3) & 1) * 8 + (lane & 7);
    const int at16 = (lane >> 4) & 1;
    const int as   = arow & 7;
    const u32 a0_lane = hs0_base + arow * 1024;
    const u32 a1_lane = hs1_base + arow * 1024;

    // cell mapping
    const int cm = tid >> 2, cj = tid & 3;
    const int col = blk * 4 + cj;
    float creg0 = 0.f, creg1 = 0.f;
    float b1g0 = bih1[0 * HH + col] + bhh1[0 * HH + col];
    float b1g1 = bih1[1 * HH + col] + bhh1[1 * HH + col];
    float b1g2 = bih1[2 * HH + col] + bhh1[2 * HH + col];
    float b1g3 = bih1[3 * HH + col] + bhh1[3 * HH + col];

    // C fragment coords
    const int crow = mt * 16 + (lane >> 2);
    const int ccol = nt * 8 + 2 * (lane & 3);

    const int srow = tid >> 6;      // staging: 4 rows/pass
    const int sc   = tid & 63;

    #pragma unroll 1
    for (int i = 0; i <= TT; ++i) {
        // prefetch xg for layer0 cell
        float x0 = 0.f, x1 = 0.f, x2 = 0.f, x3 = 0.f;
        if (i < TT) {
            const float* xp = xg + ((size_t)i * BB + cm) * GG + blk * 16 + cj;
            x0 = xp[0]; x1 = xp[4]; x2 = xp[8]; x3 = xp[12];
        }

        // ---- stage Hs0 = h0[i-1], Hs1 = h1[i-2] ----
        if (i == 0) {
            for (int r = 0; r < 16; ++r) {
                int row = r * 4 + srow;
                u32 off = row * 1024 + ((u32)(sc ^ (row & 7))) * 16;
                *(uint4*)(smraw + HS0_OFF + off) = make_uint4(0u, 0u, 0u, 0u);
                *(uint4*)(smraw + HS1_OFF + off) = make_uint4(0u, 0u, 0u, 0u);
            }
        } else {
            const __half* hp0 = h016 + (size_t)(i - 1) * BB * HH;
            #pragma unroll
            for (int r = 0; r < 16; ++r) {
                int row = r * 4 + srow;
                uint4 v = *(const uint4*)(hp0 + (size_t)row * HH + sc * 8);
                u32 off = row * 1024 + ((u32)(sc ^ (row & 7))) * 16;
                *(uint4*)(smraw + HS0_OFF + off) = v;
            }
            if (i == 1) {
                for (int r = 0; r < 16; ++r) {
                    int row = r * 4 + srow;
                    u32 off = row * 1024 + ((u32)(sc ^ (row & 7))) * 16;
                    *(uint4*)(smraw + HS1_OFF + off) = make_uint4(0u, 0u, 0u, 0u);
                }
            } else {
                const __half* hp1 = h116 + (size_t)(i - 2) * BB * HH;
                #pragma unroll
                for (int r = 0; r < 16; ++r) {
                    int row = r * 4 + srow;
                    uint4 v = *(const uint4*)(hp1 + (size_t)row * HH + sc * 8);
                    u32 off = row * 1024 + ((u32)(sc ^ (row & 7))) * 16;
                    *(uint4*)(smraw + HS1_OFF + off) = v;
                }
            }
        }
        __syncthreads();

        // ---- layer0 MMA: gates0 = Hs0 @ B0^T ----
        if (i < TT) {
            float c0 = 0.f, c1 = 0.f, c2 = 0.f, c3 = 0.f;
            #pragma unroll
            for (int kt = 0; kt < 32; ++kt) {
                u32 ch = (u32)((2 * kt + at16) ^ as);
                u32 a0, a1, a2, a3;
                ldsm_x4(a0, a1, a2, a3, a0_lane + ch * 16);
                mma16816(c0, c1, c2, c3, a0, a1, a2, a3, bf0[kt], bf1[kt]);
            }
            *(float2*)&gates0[crow * 18 + ccol]       = make_float2(c0, c1);
            *(float2*)&gates0[(crow + 8) * 18 + ccol] = make_float2(c2, c3);
        }

        // ---- layer1 MMA: gates1 = Hs1 @ B1A^T + Hs0 @ B1B^T ----
        if (i >= 1) {
            float d0 = 0.f, d1 = 0.f, d2 = 0.f, d3 = 0.f;
            #pragma unroll
            for (int kt = 0; kt < 32; ++kt) {
                u32 ch = (u32)((2 * kt + at16) ^ as);
                u32 a0, a1, a2, a3, bb0, bb1;
                ldsm_x4(a0, a1, a2, a3, a1_lane + ch * 16);
                u32 bch = (u32)((2 * kt + btsel) ^ bsw);
                ldsm_x2(bb0, bb1, b1a_lane + bch * 16);
                mma16816(d0, d1, d2, d3, a0, a1, a2, a3, bb0, bb1);
            }
            #pragma unroll
            for (int kt = 0; kt < 32; ++kt) {
                u32 ch = (u32)((2 * kt + at16) ^ as);
                u32 a0, a1, a2, a3, bb0, bb1;
                ldsm_x4(a0, a1, a2, a3, a0_lane + ch * 16);
                u32 bch = (u32)((2 * kt + btsel) ^ bsw);
                ldsm_x2(bb0, bb1, b1b_lane + bch * 16);
                mma16816(d0, d1, d2, d3, a0, a1, a2, a3, bb0, bb1);
            }
            *(float2*)&gates1[crow * 18 + ccol]       = make_float2(d0, d1);
            *(float2*)&gates1[(crow + 8) * 18 + ccol] = make_float2(d2, d3);
        }
        __syncthreads();

        // ---- cells ----
        if (i < TT) {
            const float* gp = gates0 + cm * 18 + cj;
            float gi_ = sigf (gp[0]  + x0);
            float gf_ = sigf (gp[4]  + x1);
            float gz_ = tanhf(gp[8]  + x2);
            float go_ = sigf (gp[12] + x3);
            creg0 = gf_ * creg0 + gi_ * gz_;
            float h = go_ * tanhf(creg0);
            h016[((size_t)i * BB + cm) * HH + col] = __float2half(h);
        }
        if (i >= 1) {
            const float* gp = gates1 + cm * 18 + cj;
            float gi_ = sigf (gp[0]  + b1g0);
            float gf_ = sigf (gp[4]  + b1g1);
            float gz_ = tanhf(gp[8]  + b1g2);
            float go_ = sigf (gp[12] + b1g3);
            creg1 = gf_ * creg1 + gi_ * gz_;
            float h = go_ * tanhf(creg1);
            h116[((size_t)(i - 1) * BB + cm) * HH + col] = __float2half(h);
            if (i == TT) finalout[(size_t)cm * HH + col] = h;
        }

        // ---- grid barrier ----
        if (i < TT) {
            __syncthreads();
            if (tid == 0) st_release(&flags[blk * 8], (u32)(i + 1));
            if (tid < NBLK) {
                while (ld_acquire(&flags[tid * 8]) < (u32)(i + 1)) __nanosleep(32);
            }
            __syncthreads();
        }
    }
}

// ---------------- launch ----------------
extern "C" void kernel_launch(void* const* d_in, const int* in_sizes, int n_in,
                              void* d_out, int out_size) {
    const float* x    = (const float*)d_in[0];
    const float* Wih0 = (const float*)d_in[1];
    const float* Whh0 = (const float*)d_in[2];
    const float* bih0 = (const float*)d_in[3];
    const float* bhh0 = (const float*)d_in[4];
    const float* Wih1 = (const float*)d_in[5];
    const float* Whh1 = (const float*)d_in[6];
    const float* bih1 = (const float*)d_in[7];
    const float* bhh1 = (const float*)d_in[8];
    float* out = (float*)d_out;

    float *xTt, *xg;
    __half *h016, *h116;
    u32* flags;
    cudaGetSymbolAddress((void**)&xTt,  g_xTt);
    cudaGetSymbolAddress((void**)&xg,   g_xg);
    cudaGetSymbolAddress((void**)&h016, g_h016);
    cudaGetSymbolAddress((void**)&h116, g_h116);
    cudaGetSymbolAddress((void**)&flags, g_flag);

    cudaFuncSetAttribute(lstm_fused, cudaFuncAttributeMaxDynamicSharedMemorySize, SMEM_TOTAL);

    reset_kernel<<<1, 256>>>();

    dim3 tb(32, 8), tg(TT / 32, FF / 32, BB);
    transpose_x_kernel<<<tg, tb>>>(x);

    gemm_gates<FF><<<dim3(GG / 128, TT * BB / 128), 256>>>(xTt, Wih0, bih0, bhh0, xg);
    lstm_fused<<<NBLK, 256, SMEM_TOTAL>>>(xg, Whh0, Whh1, Wih1, bih1, bhh1,
                                          h016, h116, out, flags);
}

// round 11
// speedup vs baseline: 2.6860x; 1.1306x over previous
#include <cuda_runtime.h>
#include <cuda_fp16.h>
#include <math.h>

#define BB 64
#define FF 128
#define TT 1024
#define HH 512
#define GG 2048
#define NBLK 128

typedef unsigned long long ull;
typedef unsigned int u32;

// ---------------- device globals (no allocation allowed) ----------------
__device__ __half  g_xh  [(size_t)TT * BB * FF];   // (T*B, F) f16
__device__ float   g_xg  [(size_t)TT * BB * GG];   // layer0 gate preacts (permuted layout)
__device__ __half  g_h016[(size_t)TT * BB * HH];   // layer0 h f16 [t][m][k]
__device__ __half  g_h116[(size_t)TT * BB * HH];   // layer1 h f16 [s][m][k]
__device__ u32     g_flag[NBLK * 8];

// ---------------- helpers ----------------
__device__ __forceinline__ float sigf(float x) { return 1.f / (1.f + __expf(-x)); }

__device__ __forceinline__ void st_release(u32* p, u32 v) {
    asm volatile("st.release.gpu.global.u32 [%0], %1;" :: "l"(p), "r"(v) : "memory");
}
__device__ __forceinline__ u32 ld_acquire(const u32* p) {
    u32 v;
    asm volatile("ld.acquire.gpu.global.u32 %0, [%1];" : "=r"(v) : "l"(p) : "memory");
    return v;
}
__device__ __forceinline__ u32 smem_u32(const void* p) {
    u32 a;
    asm("{ .reg .u64 t; cvta.to.shared.u64 t, %1; cvt.u32.u64 %0, t; }" : "=r"(a) : "l"(p));
    return a;
}
__device__ __forceinline__ void ldsm_x4(u32& r0, u32& r1, u32& r2, u32& r3, u32 addr) {
    asm volatile("ldmatrix.sync.aligned.m8n8.x4.shared.b16 {%0,%1,%2,%3}, [%4];"
                 : "=r"(r0), "=r"(r1), "=r"(r2), "=r"(r3) : "r"(addr));
}
__device__ __forceinline__ void ldsm_x2(u32& r0, u32& r1, u32 addr) {
    asm volatile("ldmatrix.sync.aligned.m8n8.x2.shared.b16 {%0,%1}, [%2];"
                 : "=r"(r0), "=r"(r1) : "r"(addr));
}
__device__ __forceinline__ void mma16816(float& c0, float& c1, float& c2, float& c3,
                                         u32 a0, u32 a1, u32 a2, u32 a3, u32 b0, u32 b1) {
    asm volatile("mma.sync.aligned.m16n8k16.row.col.f32.f16.f16.f32 "
                 "{%0,%1,%2,%3}, {%4,%5,%6,%7}, {%8,%9}, {%0,%1,%2,%3};"
                 : "+f"(c0), "+f"(c1), "+f"(c2), "+f"(c3)
                 : "r"(a0), "r"(a1), "r"(a2), "r"(a3), "r"(b0), "r"(b1));
}

// ---------------- reset flags ----------------
__global__ void reset_kernel() {
    for (int e = threadIdx.x; e < NBLK * 8; e += 256) g_flag[e] = 0u;
}

// ---------------- transpose x (B,F,T) f32 -> (T*B, F) f16 ----------------
__global__ void transpose_x_kernel(const float* __restrict__ x) {
    __shared__ float tile[32][33];
    int b  = blockIdx.z;
    int t0 = blockIdx.x * 32;
    int f0 = blockIdx.y * 32;
    for (int i = threadIdx.y; i < 32; i += 8)
        tile[i][threadIdx.x] = x[(size_t)b * FF * TT + (size_t)(f0 + i) * TT + t0 + threadIdx.x];
    __syncthreads();
    for (int i = threadIdx.y; i < 32; i += 8)
        g_xh[((size_t)(t0 + i) * BB + b) * FF + f0 + threadIdx.x] =
            __float2half(tile[threadIdx.x][i]);
}

// ---------------- layer0 input GEMM (HMMA): xg = xh(M,128) @ Wih0^T + b ----------------
// M-tile 128, N-tile 64 gate-cols, K=128. Output layout:
// C[row][(hc>>2)*16 + q*4 + (hc&3)], gate n = q*512 + hc.
#define GA_OFF 0
#define GB_OFF 32768
#define GSM_TOTAL (32768 + 16384)
__global__ __launch_bounds__(256, 3)
void gemm_gates_hmma(const __half* __restrict__ Ah, const float* __restrict__ W,
                     const float* __restrict__ bih, const float* __restrict__ bhh,
                     float* __restrict__ C) {
    extern __shared__ __align__(16) char gsm[];
    const u32 asm_base = smem_u32(gsm + GA_OFF);
    const u32 bsm_base = smem_u32(gsm + GB_OFF);
    const int tid = threadIdx.x;
    const int wid = tid >> 5, lane = tid & 31;
    const int n0 = blockIdx.x * 64;
    const int m0 = blockIdx.y * 128;

    // stage A tile: 128 rows x 128 halves (16 chunks of 16B per row), XOR swizzle
    #pragma unroll
    for (int i = 0; i < 8; ++i) {
        int e = i * 256 + tid;
        int row = e >> 4, ch = e & 15;
        uint4 v = *(const uint4*)(Ah + ((size_t)(m0 + row)) * FF + ch * 8);
        *(uint4*)(gsm + GA_OFF + row * 256 + ((u32)(ch ^ (row & 7))) * 16) = v;
    }
    // stage B tile: 64 gate rows x 128 (f32 -> f16), swizzled
    #pragma unroll
    for (int i = 0; i < 4; ++i) {
        int e = i * 256 + tid;
        int row = e >> 4, ch = e & 15;
        const float* wsrc = W + (size_t)(n0 + row) * FF + ch * 8;
        float4 f0 = *(const float4*)wsrc;
        float4 f1 = *(const float4*)(wsrc + 4);
        __half2 h0 = __floats2half2_rn(f0.x, f0.y), h1 = __floats2half2_rn(f0.z, f0.w);
        __half2 h2 = __floats2half2_rn(f1.x, f1.y), h3 = __floats2half2_rn(f1.z, f1.w);
        *(uint4*)(gsm + GB_OFF + row * 256 + ((u32)(ch ^ (row & 7))) * 16) =
            make_uint4(*(u32*)&h0, *(u32*)&h1, *(u32*)&h2, *(u32*)&h3);
    }
    __syncthreads();

    // warp wid owns m-tile wid (16 rows), all 8 n-tiles, K=128 (8 k-tiles)
    const int mt = wid;
    const int arow = mt * 16 + ((lane >> 3) & 1) * 8 + (lane & 7);
    const int at16 = (lane >> 4) & 1;
    const int as   = arow & 7;
    const u32 a_lane = asm_base + arow * 256;

    const int al = lane & 15;
    const int brow_l = al & 7;          // within n-tile
    const int btsel = (al >> 3) & 1;

    float acc[8][4];
    #pragma unroll
    for (int nt = 0; nt < 8; ++nt)
        #pragma unroll
        for (int p = 0; p < 4; ++p) acc[nt][p] = 0.f;

    #pragma unroll
    for (int kt = 0; kt < 8; ++kt) {
        u32 ch = (u32)((2 * kt + at16) ^ as);
        u32 a0, a1, a2, a3;
        ldsm_x4(a0, a1, a2, a3, a_lane + ch * 16);
        #pragma unroll
        for (int nt = 0; nt < 8; ++nt) {
            int brow = nt * 8 + brow_l;
            u32 bch = (u32)((2 * kt + btsel) ^ (brow & 7));
            u32 b0, b1;
            ldsm_x2(b0, b1, bsm_base + brow * 256 + bch * 16);
            mma16816(acc[nt][0], acc[nt][1], acc[nt][2], acc[nt][3], a0, a1, a2, a3, b0, b1);
        }
    }

    // epilogue: bias + permuted store (fp32)
    const int crow = mt * 16 + (lane >> 2);
    #pragma unroll
    for (int nt = 0; nt < 8; ++nt) {
        int na = n0 + nt * 8 + 2 * (lane & 3);
        int q = na >> 9, hc = na & 511;
        size_t cb = (size_t)((hc >> 2) << 4) + q * 4 + (hc & 3);
        float ba = bih[na] + bhh[na];
        float bb = bih[na + 1] + bhh[na + 1];
        *(float2*)&C[(size_t)(m0 + crow) * GG + cb] =
            make_float2(acc[nt][0] + ba, acc[nt][1] + bb);
        *(float2*)&C[(size_t)(m0 + crow + 8) * GG + cb] =
            make_float2(acc[nt][2] + ba, acc[nt][3] + bb);
    }
}

// ---------------- fused 2-layer persistent HMMA LSTM (1-step skew) ----------------
#define HS0_OFF  0
#define HS1_OFF  65536
#define B0_OFF   131072
#define B1A_OFF  (131072 + 16384)
#define B1B_OFF  (131072 + 32768)
#define GT0_OFF  (131072 + 49152)
#define GT1_OFF  (GT0_OFF + 4608)
#define SMEM_TOTAL (GT1_OFF + 4608)

__global__ __launch_bounds__(256, 1)
void lstm_fused(const float* __restrict__ xg,
                const float* __restrict__ Whh0,
                const float* __restrict__ Whh1, const float* __restrict__ Wih1,
                const float* __restrict__ bih1, const float* __restrict__ bhh1,
                __half* __restrict__ h016, __half* __restrict__ h116,
                float* __restrict__ finalout, u32* __restrict__ flags) {
    extern __shared__ __align__(16) char smraw[];
    const u32 hs0_base = smem_u32(smraw + HS0_OFF);
    const u32 hs1_base = smem_u32(smraw + HS1_OFF);
    const u32 b0_base  = smem_u32(smraw + B0_OFF);
    const u32 b1a_base = smem_u32(smraw + B1A_OFF);
    const u32 b1b_base = smem_u32(smraw + B1B_OFF);
    float* gates0 = (float*)(smraw + GT0_OFF);      // [64][18]
    float* gates1 = (float*)(smraw + GT1_OFF);      // [64][18]

    const int tid = threadIdx.x, blk = blockIdx.x;
    const int wid = tid >> 5, lane = tid & 31;
    const int mt = wid & 3, nt = wid >> 2;

    // ---- stage the three weight slices (16 x 512 f16 each, swizzled), once ----
    for (int e = tid; e < 1024; e += 256) {
        int row = e >> 6, c = e & 63;
        size_t wr = (size_t)((row >> 2) * HH + blk * 4 + (row & 3)) * HH + c * 8;
        u32 off = row * 1024 + ((u32)(c ^ (row & 7))) * 16;
        {
            float4 f0 = *(const float4*)(Whh0 + wr);
            float4 f1 = *(const float4*)(Whh0 + wr + 4);
            __half2 h0 = __floats2half2_rn(f0.x, f0.y), h1 = __floats2half2_rn(f0.z, f0.w);
            __half2 h2 = __floats2half2_rn(f1.x, f1.y), h3 = __floats2half2_rn(f1.z, f1.w);
            *(uint4*)(smraw + B0_OFF + off) = make_uint4(*(u32*)&h0, *(u32*)&h1, *(u32*)&h2, *(u32*)&h3);
        }
        {
            float4 f0 = *(const float4*)(Whh1 + wr);
            float4 f1 = *(const float4*)(Whh1 + wr + 4);
            __half2 h0 = __floats2half2_rn(f0.x, f0.y), h1 = __floats2half2_rn(f0.z, f0.w);
            __half2 h2 = __floats2half2_rn(f1.x, f1.y), h3 = __floats2half2_rn(f1.z, f1.w);
            *(uint4*)(smraw + B1A_OFF + off) = make_uint4(*(u32*)&h0, *(u32*)&h1, *(u32*)&h2, *(u32*)&h3);
        }
        {
            float4 f0 = *(const float4*)(Wih1 + wr);
            float4 f1 = *(const float4*)(Wih1 + wr + 4);
            __half2 h0 = __floats2half2_rn(f0.x, f0.y), h1 = __floats2half2_rn(f0.z, f0.w);
            __half2 h2 = __floats2half2_rn(f1.x, f1.y), h3 = __floats2half2_rn(f1.z, f1.w);
            *(uint4*)(smraw + B1B_OFF + off) = make_uint4(*(u32*)&h0, *(u32*)&h1, *(u32*)&h2, *(u32*)&h3);
        }
    }
    __syncthreads();

    // B ldsm lane mapping (frags re-loaded per k-tile; nothing pinned in regs)
    const int al = lane & 15;
    const int brow = nt * 8 + (al & 7);
    const int btsel = (al >> 3) & 1;
    const int bsw = brow & 7;
    const u32 b0_lane  = b0_base  + brow * 1024;
    const u32 b1a_lane = b1a_base + brow * 1024;
    const u32 b1b_lane = b1b_base + brow * 1024;

    // A ldsm lane mapping
    const int arow = mt * 16 + ((lane >> 3) & 1) * 8 + (lane & 7);
    const int at16 = (lane >> 4) & 1;
    const int as   = arow & 7;
    const u32 a0_lane = hs0_base + arow * 1024;
    const u32 a1_lane = hs1_base + arow * 1024;

    // cell mapping
    const int cm = tid >> 2, cj = tid & 3;
    const int col = blk * 4 + cj;
    float creg0 = 0.f, creg1 = 0.f;
    float b1g0 = bih1[0 * HH + col] + bhh1[0 * HH + col];
    float b1g1 = bih1[1 * HH + col] + bhh1[1 * HH + col];
    float b1g2 = bih1[2 * HH + col] + bhh1[2 * HH + col];
    float b1g3 = bih1[3 * HH + col] + bhh1[3 * HH + col];

    // C fragment coords
    const int crow = mt * 16 + (lane >> 2);
    const int ccol = nt * 8 + 2 * (lane & 3);

    const int srow = tid >> 6;      // staging: 4 rows/pass
    const int sc   = tid & 63;

    #pragma unroll 1
    for (int i = 0; i <= TT; ++i) {
        // prefetch xg for layer0 cell
        float x0 = 0.f, x1 = 0.f, x2 = 0.f, x3 = 0.f;
        if (i < TT) {
            const float* xp = xg + ((size_t)i * BB + cm) * GG + blk * 16 + cj;
            x0 = xp[0]; x1 = xp[4]; x2 = xp[8]; x3 = xp[12];
        }

        // ---- stage Hs0 = h0[i-1], Hs1 = h1[i-2] ----
        if (i == 0) {
            for (int r = 0; r < 16; ++r) {
                int row = r * 4 + srow;
                u32 off = row * 1024 + ((u32)(sc ^ (row & 7))) * 16;
                *(uint4*)(smraw + HS0_OFF + off) = make_uint4(0u, 0u, 0u, 0u);
                *(uint4*)(smraw + HS1_OFF + off) = make_uint4(0u, 0u, 0u, 0u);
            }
        } else {
            const __half* hp0 = h016 + (size_t)(i - 1) * BB * HH;
            #pragma unroll
            for (int r = 0; r < 16; ++r) {
                int row = r * 4 + srow;
                uint4 v = *(const uint4*)(hp0 + (size_t)row * HH + sc * 8);
                u32 off = row * 1024 + ((u32)(sc ^ (row & 7))) * 16;
                *(uint4*)(smraw + HS0_OFF + off) = v;
            }
            if (i == 1) {
                for (int r = 0; r < 16; ++r) {
                    int row = r * 4 + srow;
                    u32 off = row * 1024 + ((u32)(sc ^ (row & 7))) * 16;
                    *(uint4*)(smraw + HS1_OFF + off) = make_uint4(0u, 0u, 0u, 0u);
                }
            } else {
                const __half* hp1 = h116 + (size_t)(i - 2) * BB * HH;
                #pragma unroll
                for (int r = 0; r < 16; ++r) {
                    int row = r * 4 + srow;
                    uint4 v = *(const uint4*)(hp1 + (size_t)row * HH + sc * 8);
                    u32 off = row * 1024 + ((u32)(sc ^ (row & 7))) * 16;
                    *(uint4*)(smraw + HS1_OFF + off) = v;
                }
            }
        }
        __syncthreads();

        // ---- layer0 MMA: gates0 = Hs0 @ B0^T (2 accumulator chains) ----
        if (i < TT) {
            float ca0 = 0.f, ca1 = 0.f, ca2 = 0.f, ca3 = 0.f;
            float cb0 = 0.f, cb1 = 0.f, cb2 = 0.f, cb3 = 0.f;
            #pragma unroll
            for (int kt = 0; kt < 32; ++kt) {
                u32 ch = (u32)((2 * kt + at16) ^ as);
                u32 a0, a1, a2, a3, bb0, bb1;
                ldsm_x4(a0, a1, a2, a3, a0_lane + ch * 16);
                u32 bch = (u32)((2 * kt + btsel) ^ bsw);
                ldsm_x2(bb0, bb1, b0_lane + bch * 16);
                if (kt & 1) mma16816(cb0, cb1, cb2, cb3, a0, a1, a2, a3, bb0, bb1);
                else        mma16816(ca0, ca1, ca2, ca3, a0, a1, a2, a3, bb0, bb1);
            }
            *(float2*)&gates0[crow * 18 + ccol]       = make_float2(ca0 + cb0, ca1 + cb1);
            *(float2*)&gates0[(crow + 8) * 18 + ccol] = make_float2(ca2 + cb2, ca3 + cb3);
        }

        // ---- layer1 MMA: gates1 = Hs1 @ B1A^T + Hs0 @ B1B^T (4 chains) ----
        if (i >= 1) {
            float d[4][4];
            #pragma unroll
            for (int s = 0; s < 4; ++s)
                #pragma unroll
                for (int p = 0; p < 4; ++p) d[s][p] = 0.f;
            #pragma unroll
            for (int kt = 0; kt < 32; ++kt) {
                u32 ch = (u32)((2 * kt + at16) ^ as);
                u32 a0, a1, a2, a3, bb0, bb1;
                ldsm_x4(a0, a1, a2, a3, a1_lane + ch * 16);
                u32 bch = (u32)((2 * kt + btsel) ^ bsw);
                ldsm_x2(bb0, bb1, b1a_lane + bch * 16);
                int s = kt & 3;
                mma16816(d[s][0], d[s][1], d[s][2], d[s][3], a0, a1, a2, a3, bb0, bb1);
            }
            #pragma unroll
            for (int kt = 0; kt < 32; ++kt) {
                u32 ch = (u32)((2 * kt + at16) ^ as);
                u32 a0, a1, a2, a3, bb0, bb1;
                ldsm_x4(a0, a1, a2, a3, a0_lane + ch * 16);
                u32 bch = (u32)((2 * kt + btsel) ^ bsw);
                ldsm_x2(bb0, bb1, b1b_lane + bch * 16);
                int s = kt & 3;
                mma16816(d[s][0], d[s][1], d[s][2], d[s][3], a0, a1, a2, a3, bb0, bb1);
            }
            *(float2*)&gates1[crow * 18 + ccol] =
                make_float2(d[0][0] + d[1][0] + d[2][0] + d[3][0],
                            d[0][1] + d[1][1] + d[2][1] + d[3][1]);
            *(float2*)&gates1[(crow + 8) * 18 + ccol] =
                make_float2(d[0][2] + d[1][2] + d[2][2] + d[3][2],
                            d[0][3] + d[1][3] + d[2][3] + d[3][3]);
        }
        __syncthreads();

        // ---- cells ----
        if (i < TT) {
            const float* gp = gates0 + cm * 18 + cj;
            float gi_ = sigf (gp[0]  + x0);
            float gf_ = sigf (gp[4]  + x1);
            float gz_ = tanhf(gp[8]  + x2);
            float go_ = sigf (gp[12] + x3);
            creg0 = gf_ * creg0 + gi_ * gz_;
            float h = go_ * tanhf(creg0);
            h016[((size_t)i * BB + cm) * HH + col] = __float2half(h);
        }
        if (i >= 1) {
            const float* gp = gates1 + cm * 18 + cj;
            float gi_ = sigf (gp[0]  + b1g0);
            float gf_ = sigf (gp[4]  + b1g1);
            float gz_ = tanhf(gp[8]  + b1g2);
            float go_ = sigf (gp[12] + b1g3);
            creg1 = gf_ * creg1 + gi_ * gz_;
            float h = go_ * tanhf(creg1);
            h116[((size_t)(i - 1) * BB + cm) * HH + col] = __float2half(h);
            if (i == TT) finalout[(size_t)cm * HH + col] = h;
        }

        // ---- grid barrier (hot spin) ----
        if (i < TT) {
            __syncthreads();
            if (tid == 0) st_release(&flags[blk * 8], (u32)(i + 1));
            if (tid < NBLK) {
                while (ld_acquire(&flags[tid * 8]) < (u32)(i + 1)) {}
            }
            __syncthreads();
        }
    }
}

// ---------------- launch ----------------
extern "C" void kernel_launch(void* const* d_in, const int* in_sizes, int n_in,
                              void* d_out, int out_size) {
    const float* x    = (const float*)d_in[0];
    const float* Wih0 = (const float*)d_in[1];
    const float* Whh0 = (const float*)d_in[2];
    const float* bih0 = (const float*)d_in[3];
    const float* bhh0 = (const float*)d_in[4];
    const float* Wih1 = (const float*)d_in[5];
    const float* Whh1 = (const float*)d_in[6];
    const float* bih1 = (const float*)d_in[7];
    const float* bhh1 = (const float*)d_in[8];
    float* out = (float*)d_out;

    float* xg;
    __half *xh, *h016, *h116;
    u32* flags;
    cudaGetSymbolAddress((void**)&xh,   g_xh);
    cudaGetSymbolAddress((void**)&xg,   g_xg);
    cudaGetSymbolAddress((void**)&h016, g_h016);
    cudaGetSymbolAddress((void**)&h116, g_h116);
    cudaGetSymbolAddress((void**)&flags, g_flag);

    cudaFuncSetAttribute(lstm_fused, cudaFuncAttributeMaxDynamicSharedMemorySize, SMEM_TOTAL);
    cudaFuncSetAttribute(gemm_gates_hmma, cudaFuncAttributeMaxDynamicSharedMemorySize, GSM_TOTAL);

    reset_kernel<<<1, 256>>>();

    dim3 tb(32, 8), tg(TT / 32, FF / 32, BB);
    transpose_x_kernel<<<tg, tb>>>(x);

    gemm_gates_hmma<<<dim3(GG / 64, TT * BB / 128), 256, GSM_TOTAL>>>(xh, Wih0, bih0, bhh0, xg);
    lstm_fused<<<NBLK, 256, SMEM_TOTAL>>>(xg, Whh0, Whh1, Wih1, bih1, bhh1,
                                          h016, h116, out, flags);
}

// round 12
// speedup vs baseline: 2.8527x; 1.0620x over previous
#include <cuda_runtime.h>
#include <cuda_fp16.h>
#include <math.h>

#define BB 64
#define FF 128
#define TT 1024
#define HH 512
#define GG 2048
#define NBLK 128

typedef unsigned long long ull;
typedef unsigned int u32;

// ---------------- device globals (no allocation allowed) ----------------
__device__ __half  g_xh  [(size_t)TT * BB * FF];   // (T*B, F) f16
__device__ float   g_xg  [(size_t)TT * BB * GG];   // layer0 gate preacts (permuted layout)
__device__ __half  g_h016[(size_t)TT * BB * HH];   // layer0 h f16 [t][m][k]
__device__ __half  g_h116[(size_t)TT * BB * HH];   // layer1 h f16 [s][m][k]
__device__ u32     g_flag[NBLK * 8];

// ---------------- helpers ----------------
__device__ __forceinline__ float sigf(float x) { return 1.f / (1.f + __expf(-x)); }

__device__ __forceinline__ void st_release(u32* p, u32 v) {
    asm volatile("st.release.gpu.global.u32 [%0], %1;" :: "l"(p), "r"(v) : "memory");
}
__device__ __forceinline__ u32 ld_acquire(const u32* p) {
    u32 v;
    asm volatile("ld.acquire.gpu.global.u32 %0, [%1];" : "=r"(v) : "l"(p) : "memory");
    return v;
}
__device__ __forceinline__ u32 smem_u32(const void* p) {
    u32 a;
    asm("{ .reg .u64 t; cvta.to.shared.u64 t, %1; cvt.u32.u64 %0, t; }" : "=r"(a) : "l"(p));
    return a;
}
__device__ __forceinline__ void ldsm_x4(u32& r0, u32& r1, u32& r2, u32& r3, u32 addr) {
    asm volatile("ldmatrix.sync.aligned.m8n8.x4.shared.b16 {%0,%1,%2,%3}, [%4];"
                 : "=r"(r0), "=r"(r1), "=r"(r2), "=r"(r3) : "r"(addr));
}
__device__ __forceinline__ void ldsm_x2(u32& r0, u32& r1, u32 addr) {
    asm volatile("ldmatrix.sync.aligned.m8n8.x2.shared.b16 {%0,%1}, [%2];"
                 : "=r"(r0), "=r"(r1) : "r"(addr));
}
__device__ __forceinline__ void mma16816(float& c0, float& c1, float& c2, float& c3,
                                         u32 a0, u32 a1, u32 a2, u32 a3, u32 b0, u32 b1) {
    asm volatile("mma.sync.aligned.m16n8k16.row.col.f32.f16.f16.f32 "
                 "{%0,%1,%2,%3}, {%4,%5,%6,%7}, {%8,%9}, {%0,%1,%2,%3};"
                 : "+f"(c0), "+f"(c1), "+f"(c2), "+f"(c3)
                 : "r"(a0), "r"(a1), "r"(a2), "r"(a3), "r"(b0), "r"(b1));
}

// ---------------- reset flags ----------------
__global__ void reset_kernel() {
    for (int e = threadIdx.x; e < NBLK * 8; e += 256) g_flag[e] = 0u;
}

// ---------------- transpose x (B,F,T) f32 -> (T*B, F) f16 ----------------
__global__ void transpose_x_kernel(const float* __restrict__ x) {
    __shared__ float tile[32][33];
    int b  = blockIdx.z;
    int t0 = blockIdx.x * 32;
    int f0 = blockIdx.y * 32;
    for (int i = threadIdx.y; i < 32; i += 8)
        tile[i][threadIdx.x] = x[(size_t)b * FF * TT + (size_t)(f0 + i) * TT + t0 + threadIdx.x];
    __syncthreads();
    for (int i = threadIdx.y; i < 32; i += 8)
        g_xh[((size_t)(t0 + i) * BB + b) * FF + f0 + threadIdx.x] =
            __float2half(tile[threadIdx.x][i]);
}

// ---------------- layer0 input GEMM (HMMA): xg = xh(M,128) @ Wih0^T + b ----------------
#define GA_OFF 0
#define GB_OFF 32768
#define GSM_TOTAL (32768 + 16384)
__global__ __launch_bounds__(256, 3)
void gemm_gates_hmma(const __half* __restrict__ Ah, const float* __restrict__ W,
                     const float* __restrict__ bih, const float* __restrict__ bhh,
                     float* __restrict__ C) {
    extern __shared__ __align__(16) char gsm[];
    const u32 asm_base = smem_u32(gsm + GA_OFF);
    const u32 bsm_base = smem_u32(gsm + GB_OFF);
    const int tid = threadIdx.x;
    const int wid = tid >> 5, lane = tid & 31;
    const int n0 = blockIdx.x * 64;
    const int m0 = blockIdx.y * 128;

    #pragma unroll
    for (int i = 0; i < 8; ++i) {
        int e = i * 256 + tid;
        int row = e >> 4, ch = e & 15;
        uint4 v = *(const uint4*)(Ah + ((size_t)(m0 + row)) * FF + ch * 8);
        *(uint4*)(gsm + GA_OFF + row * 256 + ((u32)(ch ^ (row & 7))) * 16) = v;
    }
    #pragma unroll
    for (int i = 0; i < 4; ++i) {
        int e = i * 256 + tid;
        int row = e >> 4, ch = e & 15;
        const float* wsrc = W + (size_t)(n0 + row) * FF + ch * 8;
        float4 f0 = *(const float4*)wsrc;
        float4 f1 = *(const float4*)(wsrc + 4);
        __half2 h0 = __floats2half2_rn(f0.x, f0.y), h1 = __floats2half2_rn(f0.z, f0.w);
        __half2 h2 = __floats2half2_rn(f1.x, f1.y), h3 = __floats2half2_rn(f1.z, f1.w);
        *(uint4*)(gsm + GB_OFF + row * 256 + ((u32)(ch ^ (row & 7))) * 16) =
            make_uint4(*(u32*)&h0, *(u32*)&h1, *(u32*)&h2, *(u32*)&h3);
    }
    __syncthreads();

    const int mt = wid;
    const int arow = mt * 16 + ((lane >> 3) & 1) * 8 + (lane & 7);
    const int at16 = (lane >> 4) & 1;
    const int as   = arow & 7;
    const u32 a_lane = asm_base + arow * 256;

    const int al = lane & 15;
    const int brow_l = al & 7;
    const int btsel = (al >> 3) & 1;

    float acc[8][4];
    #pragma unroll
    for (int nt = 0; nt < 8; ++nt)
        #pragma unroll
        for (int p = 0; p < 4; ++p) acc[nt][p] = 0.f;

    #pragma unroll
    for (int kt = 0; kt < 8; ++kt) {
        u32 ch = (u32)((2 * kt + at16) ^ as);
        u32 a0, a1, a2, a3;
        ldsm_x4(a0, a1, a2, a3, a_lane + ch * 16);
        #pragma unroll
        for (int nt = 0; nt < 8; ++nt) {
            int brow = nt * 8 + brow_l;
            u32 bch = (u32)((2 * kt + btsel) ^ (brow & 7));
            u32 b0, b1;
            ldsm_x2(b0, b1, bsm_base + brow * 256 + bch * 16);
            mma16816(acc[nt][0], acc[nt][1], acc[nt][2], acc[nt][3], a0, a1, a2, a3, b0, b1);
        }
    }

    const int crow = mt * 16 + (lane >> 2);
    #pragma unroll
    for (int nt = 0; nt < 8; ++nt) {
        int na = n0 + nt * 8 + 2 * (lane & 3);
        int q = na >> 9, hc = na & 511;
        size_t cb = (size_t)((hc >> 2) << 4) + q * 4 + (hc & 3);
        float ba = bih[na] + bhh[na];
        float bb = bih[na + 1] + bhh[na + 1];
        *(float2*)&C[(size_t)(m0 + crow) * GG + cb] =
            make_float2(acc[nt][0] + ba, acc[nt][1] + bb);
        *(float2*)&C[(size_t)(m0 + crow + 8) * GG + cb] =
            make_float2(acc[nt][2] + ba, acc[nt][3] + bb);
    }
}

// ---------------- fused 2-layer persistent HMMA LSTM (1-step skew) ----------------
// 512 threads / 16 warps, warp = (mt 0..3, kh 0..3): m16 x n16 x quarter-K.
// 4 kh-partials per layer summed by the cell threads.
#define HS0_OFF  0
#define HS1_OFF  65536
#define B0_OFF   131072
#define B1A_OFF  (131072 + 16384)
#define B1B_OFF  (131072 + 32768)
#define GT0_OFF  (131072 + 49152)             // [4][64][18] f32 = 18432B
#define GT1_OFF  (GT0_OFF + 18432)
#define SMEM_TOTAL (GT1_OFF + 18432)

__global__ __launch_bounds__(512, 1)
void lstm_fused(const float* __restrict__ xg,
                const float* __restrict__ Whh0,
                const float* __restrict__ Whh1, const float* __restrict__ Wih1,
                const float* __restrict__ bih1, const float* __restrict__ bhh1,
                __half* __restrict__ h016, __half* __restrict__ h116,
                float* __restrict__ finalout, u32* __restrict__ flags) {
    extern __shared__ __align__(16) char smraw[];
    const u32 hs0_base = smem_u32(smraw + HS0_OFF);
    const u32 hs1_base = smem_u32(smraw + HS1_OFF);
    const u32 b0_base  = smem_u32(smraw + B0_OFF);
    const u32 b1a_base = smem_u32(smraw + B1A_OFF);
    const u32 b1b_base = smem_u32(smraw + B1B_OFF);
    float* gates0 = (float*)(smraw + GT0_OFF);      // [4][64][18]
    float* gates1 = (float*)(smraw + GT1_OFF);      // [4][64][18]

    const int tid = threadIdx.x, blk = blockIdx.x;
    const int wid = tid >> 5, lane = tid & 31;
    const int mt = wid & 3, kh = wid >> 2;          // kh 0..3 (K quarter)

    // ---- stage the three weight slices (16 x 512 f16 each, swizzled), once ----
    for (int e = tid; e < 1024; e += 512) {
        int row = e >> 6, c = e & 63;
        size_t wr = (size_t)((row >> 2) * HH + blk * 4 + (row & 3)) * HH + c * 8;
        u32 off = row * 1024 + ((u32)(c ^ (row & 7))) * 16;
        {
            float4 f0 = *(const float4*)(Whh0 + wr);
            float4 f1 = *(const float4*)(Whh0 + wr + 4);
            __half2 h0 = __floats2half2_rn(f0.x, f0.y), h1 = __floats2half2_rn(f0.z, f0.w);
            __half2 h2 = __floats2half2_rn(f1.x, f1.y), h3 = __floats2half2_rn(f1.z, f1.w);
            *(uint4*)(smraw + B0_OFF + off) = make_uint4(*(u32*)&h0, *(u32*)&h1, *(u32*)&h2, *(u32*)&h3);
        }
        {
            float4 f0 = *(const float4*)(Whh1 + wr);
            float4 f1 = *(const float4*)(Whh1 + wr + 4);
            __half2 h0 = __floats2half2_rn(f0.x, f0.y), h1 = __floats2half2_rn(f0.z, f0.w);
            __half2 h2 = __floats2half2_rn(f1.x, f1.y), h3 = __floats2half2_rn(f1.z, f1.w);
            *(uint4*)(smraw + B1A_OFF + off) = make_uint4(*(u32*)&h0, *(u32*)&h1, *(u32*)&h2, *(u32*)&h3);
        }
        {
            float4 f0 = *(const float4*)(Wih1 + wr);
            float4 f1 = *(const float4*)(Wih1 + wr + 4);
            __half2 h0 = __floats2half2_rn(f0.x, f0.y), h1 = __floats2half2_rn(f0.z, f0.w);
            __half2 h2 = __floats2half2_rn(f1.x, f1.y), h3 = __floats2half2_rn(f1.z, f1.w);
            *(uint4*)(smraw + B1B_OFF + off) = make_uint4(*(u32*)&h0, *(u32*)&h1, *(u32*)&h2, *(u32*)&h3);
        }
    }
    __syncthreads();

    // B ldsm lane mapping: n16 = two 8-row tiles (rows 0-7 and 8-15)
    const int al = lane & 15;
    const int brow0 = al & 7;                 // also == brow&7 for both tiles
    const int btsel = (al >> 3) & 1;
    const u32 b0_l0  = b0_base  + brow0 * 1024;
    const u32 b0_l1  = b0_base  + (brow0 + 8) * 1024;
    const u32 b1a_l0 = b1a_base + brow0 * 1024;
    const u32 b1a_l1 = b1a_base + (brow0 + 8) * 1024;
    const u32 b1b_l0 = b1b_base + brow0 * 1024;
    const u32 b1b_l1 = b1b_base + (brow0 + 8) * 1024;

    // A ldsm lane mapping
    const int arow = mt * 16 + ((lane >> 3) & 1) * 8 + (lane & 7);
    const int at16 = (lane >> 4) & 1;
    const int as   = arow & 7;
    const u32 a0_lane = hs0_base + arow * 1024;
    const u32 a1_lane = hs1_base + arow * 1024;

    // cell mapping (tid < 256)
    const int cm = tid >> 2, cj = tid & 3;
    const int col = blk * 4 + cj;
    float creg0 = 0.f, creg1 = 0.f;
    float b1g0 = 0.f, b1g1 = 0.f, b1g2 = 0.f, b1g3 = 0.f;
    if (tid < 256) {
        b1g0 = bih1[0 * HH + col] + bhh1[0 * HH + col];
        b1g1 = bih1[1 * HH + col] + bhh1[1 * HH + col];
        b1g2 = bih1[2 * HH + col] + bhh1[2 * HH + col];
        b1g3 = bih1[3 * HH + col] + bhh1[3 * HH + col];
    }

    // C fragment coords; partial buffers for this kh
    const int crow = mt * 16 + (lane >> 2);
    const int cc   = 2 * (lane & 3);
    float* g0p = gates0 + kh * (64 * 18);
    float* g1p = gates1 + kh * (64 * 18);

    #pragma unroll 1
    for (int i = 0; i <= TT; ++i) {
        // prefetch xg for layer0 cell
        float x0 = 0.f, x1 = 0.f, x2 = 0.f, x3 = 0.f;
        if (tid < 256 && i < TT) {
            const float* xp = xg + ((size_t)i * BB + cm) * GG + blk * 16 + cj;
            x0 = xp[0]; x1 = xp[4]; x2 = xp[8]; x3 = xp[12];
        }

        // ---- stage Hs0 = h0[i-1], Hs1 = h1[i-2] (512-thread mapping) ----
        if (i == 0) {
            #pragma unroll
            for (int r = 0; r < 8; ++r) {
                int e = r * 512 + tid;
                int row = e >> 6, sc = e & 63;
                u32 off = row * 1024 + ((u32)(sc ^ (row & 7))) * 16;
                *(uint4*)(smraw + HS0_OFF + off) = make_uint4(0u, 0u, 0u, 0u);
                *(uint4*)(smraw + HS1_OFF + off) = make_uint4(0u, 0u, 0u, 0u);
            }
        } else {
            const __half* hp0 = h016 + (size_t)(i - 1) * BB * HH;
            #pragma unroll
            for (int r = 0; r < 8; ++r) {
                int e = r * 512 + tid;
                int row = e >> 6, sc = e & 63;
                uint4 v = *(const uint4*)(hp0 + (size_t)row * HH + sc * 8);
                u32 off = row * 1024 + ((u32)(sc ^ (row & 7))) * 16;
                *(uint4*)(smraw + HS0_OFF + off) = v;
            }
            if (i == 1) {
                #pragma unroll
                for (int r = 0; r < 8; ++r) {
                    int e = r * 512 + tid;
                    int row = e >> 6, sc = e & 63;
                    u32 off = row * 1024 + ((u32)(sc ^ (row & 7))) * 16;
                    *(uint4*)(smraw + HS1_OFF + off) = make_uint4(0u, 0u, 0u, 0u);
                }
            } else {
                const __half* hp1 = h116 + (size_t)(i - 2) * BB * HH;
                #pragma unroll
                for (int r = 0; r < 8; ++r) {
                    int e = r * 512 + tid;
                    int row = e >> 6, sc = e & 63;
                    uint4 v = *(const uint4*)(hp1 + (size_t)row * HH + sc * 8);
                    u32 off = row * 1024 + ((u32)(sc ^ (row & 7))) * 16;
                    *(uint4*)(smraw + HS1_OFF + off) = v;
                }
            }
        }
        __syncthreads();

        // ---- layer0: partial gates0 = Hs0[kh quarter] @ B0^T (m16 x n16) ----
        if (i < TT) {
            float c00 = 0.f, c01 = 0.f, c02 = 0.f, c03 = 0.f;
            float c10 = 0.f, c11 = 0.f, c12 = 0.f, c13 = 0.f;
            #pragma unroll
            for (int j = 0; j < 8; ++j) {
                int kt = kh * 8 + j;
                u32 ch  = (u32)((2 * kt + at16) ^ as);
                u32 bch = (u32)((2 * kt + btsel) ^ brow0);
                u32 a0, a1, a2, a3, b0, b1;
                ldsm_x4(a0, a1, a2, a3, a0_lane + ch * 16);
                ldsm_x2(b0, b1, b0_l0 + bch * 16);
                mma16816(c00, c01, c02, c03, a0, a1, a2, a3, b0, b1);
                ldsm_x2(b0, b1, b0_l1 + bch * 16);
                mma16816(c10, c11, c12, c13, a0, a1, a2, a3, b0, b1);
            }
            *(float2*)&g0p[crow * 18 + cc]           = make_float2(c00, c01);
            *(float2*)&g0p[(crow + 8) * 18 + cc]     = make_float2(c02, c03);
            *(float2*)&g0p[crow * 18 + 8 + cc]       = make_float2(c10, c11);
            *(float2*)&g0p[(crow + 8) * 18 + 8 + cc] = make_float2(c12, c13);
        }

        // ---- layer1: partial gates1 = Hs1 @ B1A^T + Hs0 @ B1B^T ----
        if (i >= 1) {
            float d00 = 0.f, d01 = 0.f, d02 = 0.f, d03 = 0.f;
            float d10 = 0.f, d11 = 0.f, d12 = 0.f, d13 = 0.f;
            #pragma unroll
            for (int j = 0; j < 8; ++j) {
                int kt = kh * 8 + j;
                u32 ch  = (u32)((2 * kt + at16) ^ as);
                u32 bch = (u32)((2 * kt + btsel) ^ brow0);
                u32 a0, a1, a2, a3, b0, b1;
                ldsm_x4(a0, a1, a2, a3, a1_lane + ch * 16);
                ldsm_x2(b0, b1, b1a_l0 + bch * 16);
                mma16816(d00, d01, d02, d03, a0, a1, a2, a3, b0, b1);
                ldsm_x2(b0, b1, b1a_l1 + bch * 16);
                mma16816(d10, d11, d12, d13, a0, a1, a2, a3, b0, b1);
            }
            #pragma unroll
            for (int j = 0; j < 8; ++j) {
                int kt = kh * 8 + j;
                u32 ch  = (u32)((2 * kt + at16) ^ as);
                u32 bch = (u32)((2 * kt + btsel) ^ brow0);
                u32 a0, a1, a2, a3, b0, b1;
                ldsm_x4(a0, a1, a2, a3, a0_lane + ch * 16);
                ldsm_x2(b0, b1, b1b_l0 + bch * 16);
                mma16816(d00, d01, d02, d03, a0, a1, a2, a3, b0, b1);
                ldsm_x2(b0, b1, b1b_l1 + bch * 16);
                mma16816(d10, d11, d12, d13, a0, a1, a2, a3, b0, b1);
            }
            *(float2*)&g1p[crow * 18 + cc]           = make_float2(d00, d01);
            *(float2*)&g1p[(crow + 8) * 18 + cc]     = make_float2(d02, d03);
            *(float2*)&g1p[crow * 18 + 8 + cc]       = make_float2(d10, d11);
            *(float2*)&g1p[(crow + 8) * 18 + 8 + cc] = make_float2(d12, d13);
        }
        __syncthreads();

        // ---- cells (tid < 256): sum 4 kh-partials per gate ----
        if (tid < 256) {
            if (i < TT) {
                const float* gp = gates0 + cm * 18 + cj;
                float s0 = gp[0]    + gp[1152]    + gp[2304]    + gp[3456];
                float s1 = gp[4]    + gp[1156]    + gp[2308]    + gp[3460];
                float s2 = gp[8]    + gp[1160]    + gp[2312]    + gp[3464];
                float s3 = gp[12]   + gp[1164]    + gp[2316]    + gp[3468];
                float gi_ = sigf (s0 + x0);
                float gf_ = sigf (s1 + x1);
                float gz_ = tanhf(s2 + x2);
                float go_ = sigf (s3 + x3);
                creg0 = gf_ * creg0 + gi_ * gz_;
                float h = go_ * tanhf(creg0);
                h016[((size_t)i * BB + cm) * HH + col] = __float2half(h);
            }
            if (i >= 1) {
                const float* gp = gates1 + cm * 18 + cj;
                float s0 = gp[0]    + gp[1152]    + gp[2304]    + gp[3456];
                float s1 = gp[4]    + gp[1156]    + gp[2308]    + gp[3460];
                float s2 = gp[8]    + gp[1160]    + gp[2312]    + gp[3464];
                float s3 = gp[12]   + gp[1164]    + gp[2316]    + gp[3468];
                float gi_ = sigf (s0 + b1g0);
                float gf_ = sigf (s1 + b1g1);
                float gz_ = tanhf(s2 + b1g2);
                float go_ = sigf (s3 + b1g3);
                creg1 = gf_ * creg1 + gi_ * gz_;
                float h = go_ * tanhf(creg1);
                h116[((size_t)(i - 1) * BB + cm) * HH + col] = __float2half(h);
                if (i == TT) finalout[(size_t)cm * HH + col] = h;
            }
        }

        // ---- grid barrier ----
        if (i < TT) {
            __syncthreads();
            if (tid == 0) st_release(&flags[blk * 8], (u32)(i + 1));
            if (tid < NBLK) {
                while (ld_acquire(&flags[tid * 8]) < (u32)(i + 1)) {}
            }
            __syncthreads();
        }
    }
}

// ---------------- launch ----------------
extern "C" void kernel_launch(void* const* d_in, const int* in_sizes, int n_in,
                              void* d_out, int out_size) {
    const float* x    = (const float*)d_in[0];
    const float* Wih0 = (const float*)d_in[1];
    const float* Whh0 = (const float*)d_in[2];
    const float* bih0 = (const float*)d_in[3];
    const float* bhh0 = (const float*)d_in[4];
    const float* Wih1 = (const float*)d_in[5];
    const float* Whh1 = (const float*)d_in[6];
    const float* bih1 = (const float*)d_in[7];
    const float* bhh1 = (const float*)d_in[8];
    float* out = (float*)d_out;

    float* xg;
    __half *xh, *h016, *h116;
    u32* flags;
    cudaGetSymbolAddress((void**)&xh,   g_xh);
    cudaGetSymbolAddress((void**)&xg,   g_xg);
    cudaGetSymbolAddress((void**)&h016, g_h016);
    cudaGetSymbolAddress((void**)&h116, g_h116);
    cudaGetSymbolAddress((void**)&flags, g_flag);

    cudaFuncSetAttribute(lstm_fused, cudaFuncAttributeMaxDynamicSharedMemorySize, SMEM_TOTAL);
    cudaFuncSetAttribute(gemm_gates_hmma, cudaFuncAttributeMaxDynamicSharedMemorySize, GSM_TOTAL);

    reset_kernel<<<1, 256>>>();

    dim3 tb(32, 8), tg(TT / 32, FF / 32, BB);
    transpose_x_kernel<<<tg, tb>>>(x);

    gemm_gates_hmma<<<dim3(GG / 64, TT * BB / 128), 256, GSM_TOTAL>>>(xh, Wih0, bih0, bhh0, xg);
    lstm_fused<<<NBLK, 512, SMEM_TOTAL>>>(xg, Whh0, Whh1, Wih1, bih1, bhh1,
                                          h016, h116, out, flags);
}

// round 13
// speedup vs baseline: 3.7696x; 1.3214x over previous
#include <cuda_runtime.h>
#include <cuda_fp16.h>
#include <math.h>

#define BB 64
#define FF 128
#define TT 1024
#define HH 512
#define GG 2048
#define NBLK 128

typedef unsigned long long ull;
typedef unsigned int u32;

// ---------------- device globals (no allocation allowed) ----------------
__device__ __half  g_xh  [(size_t)TT * BB * FF];   // (T*B, F) f16
__device__ float   g_xg  [(size_t)TT * BB * GG];   // layer0 gate preacts (permuted layout)
__device__ __half  g_h016[(size_t)TT * BB * HH];   // layer0 h f16 [t][m][k]
__device__ __half  g_h116[(size_t)TT * BB * HH];   // layer1 h f16 [s][m][k]
__device__ u32     g_cnt;                          // barrier counter

// ---------------- helpers ----------------
__device__ __forceinline__ float sigf(float x) { return 1.f / (1.f + __expf(-x)); }

__device__ __forceinline__ void red_release_add(u32* p, u32 v) {
    asm volatile("red.release.gpu.global.add.u32 [%0], %1;" :: "l"(p), "r"(v) : "memory");
}
__device__ __forceinline__ u32 ld_acquire(const u32* p) {
    u32 v;
    asm volatile("ld.acquire.gpu.global.u32 %0, [%1];" : "=r"(v) : "l"(p) : "memory");
    return v;
}
__device__ __forceinline__ u32 smem_u32(const void* p) {
    u32 a;
    asm("{ .reg .u64 t; cvta.to.shared.u64 t, %1; cvt.u32.u64 %0, t; }" : "=r"(a) : "l"(p));
    return a;
}
__device__ __forceinline__ void ldsm_x4(u32& r0, u32& r1, u32& r2, u32& r3, u32 addr) {
    asm volatile("ldmatrix.sync.aligned.m8n8.x4.shared.b16 {%0,%1,%2,%3}, [%4];"
                 : "=r"(r0), "=r"(r1), "=r"(r2), "=r"(r3) : "r"(addr));
}
__device__ __forceinline__ void ldsm_x2(u32& r0, u32& r1, u32 addr) {
    asm volatile("ldmatrix.sync.aligned.m8n8.x2.shared.b16 {%0,%1}, [%2];"
                 : "=r"(r0), "=r"(r1) : "r"(addr));
}
__device__ __forceinline__ void mma16816(float& c0, float& c1, float& c2, float& c3,
                                         u32 a0, u32 a1, u32 a2, u32 a3, u32 b0, u32 b1) {
    asm volatile("mma.sync.aligned.m16n8k16.row.col.f32.f16.f16.f32 "
                 "{%0,%1,%2,%3}, {%4,%5,%6,%7}, {%8,%9}, {%0,%1,%2,%3};"
                 : "+f"(c0), "+f"(c1), "+f"(c2), "+f"(c3)
                 : "r"(a0), "r"(a1), "r"(a2), "r"(a3), "r"(b0), "r"(b1));
}

// ---------------- reset counter ----------------
__global__ void reset_kernel() {
    if (threadIdx.x == 0) g_cnt = 0u;
}

// ---------------- transpose x (B,F,T) f32 -> (T*B, F) f16 ----------------
__global__ void transpose_x_kernel(const float* __restrict__ x) {
    __shared__ float tile[32][33];
    int b  = blockIdx.z;
    int t0 = blockIdx.x * 32;
    int f0 = blockIdx.y * 32;
    for (int i = threadIdx.y; i < 32; i += 8)
        tile[i][threadIdx.x] = x[(size_t)b * FF * TT + (size_t)(f0 + i) * TT + t0 + threadIdx.x];
    __syncthreads();
    for (int i = threadIdx.y; i < 32; i += 8)
        g_xh[((size_t)(t0 + i) * BB + b) * FF + f0 + threadIdx.x] =
            __float2half(tile[threadIdx.x][i]);
}

// ---------------- layer0 input GEMM (HMMA): xg = xh(M,128) @ Wih0^T + b ----------------
#define GA_OFF 0
#define GB_OFF 32768
#define GSM_TOTAL (32768 + 16384)
__global__ __launch_bounds__(256, 3)
void gemm_gates_hmma(const __half* __restrict__ Ah, const float* __restrict__ W,
                     const float* __restrict__ bih, const float* __restrict__ bhh,
                     float* __restrict__ C) {
    extern __shared__ __align__(16) char gsm[];
    const u32 asm_base = smem_u32(gsm + GA_OFF);
    const u32 bsm_base = smem_u32(gsm + GB_OFF);
    const int tid = threadIdx.x;
    const int wid = tid >> 5, lane = tid & 31;
    const int n0 = blockIdx.x * 64;
    const int m0 = blockIdx.y * 128;

    #pragma unroll
    for (int i = 0; i < 8; ++i) {
        int e = i * 256 + tid;
        int row = e >> 4, ch = e & 15;
        uint4 v = *(const uint4*)(Ah + ((size_t)(m0 + row)) * FF + ch * 8);
        *(uint4*)(gsm + GA_OFF + row * 256 + ((u32)(ch ^ (row & 7))) * 16) = v;
    }
    #pragma unroll
    for (int i = 0; i < 4; ++i) {
        int e = i * 256 + tid;
        int row = e >> 4, ch = e & 15;
        const float* wsrc = W + (size_t)(n0 + row) * FF + ch * 8;
        float4 f0 = *(const float4*)wsrc;
        float4 f1 = *(const float4*)(wsrc + 4);
        __half2 h0 = __floats2half2_rn(f0.x, f0.y), h1 = __floats2half2_rn(f0.z, f0.w);
        __half2 h2 = __floats2half2_rn(f1.x, f1.y), h3 = __floats2half2_rn(f1.z, f1.w);
        *(uint4*)(gsm + GB_OFF + row * 256 + ((u32)(ch ^ (row & 7))) * 16) =
            make_uint4(*(u32*)&h0, *(u32*)&h1, *(u32*)&h2, *(u32*)&h3);
    }
    __syncthreads();

    const int mt = wid;
    const int arow = mt * 16 + ((lane >> 3) & 1) * 8 + (lane & 7);
    const int at16 = (lane >> 4) & 1;
    const int as   = arow & 7;
    const u32 a_lane = asm_base + arow * 256;

    const int al = lane & 15;
    const int brow_l = al & 7;
    const int btsel = (al >> 3) & 1;

    float acc[8][4];
    #pragma unroll
    for (int nt = 0; nt < 8; ++nt)
        #pragma unroll
        for (int p = 0; p < 4; ++p) acc[nt][p] = 0.f;

    #pragma unroll
    for (int kt = 0; kt < 8; ++kt) {
        u32 ch = (u32)((2 * kt + at16) ^ as);
        u32 a0, a1, a2, a3;
        ldsm_x4(a0, a1, a2, a3, a_lane + ch * 16);
        #pragma unroll
        for (int nt = 0; nt < 8; ++nt) {
            int brow = nt * 8 + brow_l;
            u32 bch = (u32)((2 * kt + btsel) ^ (brow & 7));
            u32 b0, b1;
            ldsm_x2(b0, b1, bsm_base + brow * 256 + bch * 16);
            mma16816(acc[nt][0], acc[nt][1], acc[nt][2], acc[nt][3], a0, a1, a2, a3, b0, b1);
        }
    }

    const int crow = mt * 16 + (lane >> 2);
    #pragma unroll
    for (int nt = 0; nt < 8; ++nt) {
        int na = n0 + nt * 8 + 2 * (lane & 3);
        int q = na >> 9, hc = na & 511;
        size_t cb = (size_t)((hc >> 2) << 4) + q * 4 + (hc & 3);
        float ba = bih[na] + bhh[na];
        float bb = bih[na + 1] + bhh[na + 1];
        *(float2*)&C[(size_t)(m0 + crow) * GG + cb] =
            make_float2(acc[nt][0] + ba, acc[nt][1] + bb);
        *(float2*)&C[(size_t)(m0 + crow + 8) * GG + cb] =
            make_float2(acc[nt][2] + ba, acc[nt][3] + bb);
    }
}

// ---------------- fused 2-layer persistent HMMA LSTM (1-step skew) ----------------
// 512 threads / 16 warps, warp = (mt 0..3, kh 0..3): m16 x n16 x quarter-K.
// A0 fragments shared between layer0 (B0) and layer1 input half (B1B).
// B staged with row n = j*4+q so the cell reduces with float4 loads.
// Single-counter red.release barrier.
#define HS0_OFF  0
#define HS1_OFF  65536
#define B0_OFF   131072
#define B1A_OFF  (131072 + 16384)
#define B1B_OFF  (131072 + 32768)
#define GT0_OFF  (131072 + 49152)             // [4][64][20] f32 = 20480B
#define GT1_OFF  (GT0_OFF + 20480)
#define SMEM_TOTAL (GT1_OFF + 20480)

__global__ __launch_bounds__(512, 1)
void lstm_fused(const float* __restrict__ xg,
                const float* __restrict__ Whh0,
                const float* __restrict__ Whh1, const float* __restrict__ Wih1,
                const float* __restrict__ bih1, const float* __restrict__ bhh1,
                __half* __restrict__ h016, __half* __restrict__ h116,
                float* __restrict__ finalout, u32* __restrict__ cnt) {
    extern __shared__ __align__(16) char smraw[];
    const u32 hs0_base = smem_u32(smraw + HS0_OFF);
    const u32 hs1_base = smem_u32(smraw + HS1_OFF);
    const u32 b0_base  = smem_u32(smraw + B0_OFF);
    const u32 b1a_base = smem_u32(smraw + B1A_OFF);
    const u32 b1b_base = smem_u32(smraw + B1B_OFF);
    float* gates0 = (float*)(smraw + GT0_OFF);      // [4][64][20]
    float* gates1 = (float*)(smraw + GT1_OFF);      // [4][64][20]

    const int tid = threadIdx.x, blk = blockIdx.x;
    const int wid = tid >> 5, lane = tid & 31;
    const int mt = wid & 3, kh = wid >> 2;          // kh 0..3 (K quarter)

    // ---- stage the three weight slices (16 x 512 f16 each, swizzled), once ----
    // Staged row n corresponds to weight row (q = n&3)*HH + blk*4 + (j = n>>2).
    for (int e = tid; e < 1024; e += 512) {
        int row = e >> 6, c = e & 63;
        size_t wr = (size_t)((row & 3) * HH + blk * 4 + (row >> 2)) * HH + c * 8;
        u32 off = row * 1024 + ((u32)(c ^ (row & 7))) * 16;
        {
            float4 f0 = *(const float4*)(Whh0 + wr);
            float4 f1 = *(const float4*)(Whh0 + wr + 4);
            __half2 h0 = __floats2half2_rn(f0.x, f0.y), h1 = __floats2half2_rn(f0.z, f0.w);
            __half2 h2 = __floats2half2_rn(f1.x, f1.y), h3 = __floats2half2_rn(f1.z, f1.w);
            *(uint4*)(smraw + B0_OFF + off) = make_uint4(*(u32*)&h0, *(u32*)&h1, *(u32*)&h2, *(u32*)&h3);
        }
        {
            float4 f0 = *(const float4*)(Whh1 + wr);
            float4 f1 = *(const float4*)(Whh1 + wr + 4);
            __half2 h0 = __floats2half2_rn(f0.x, f0.y), h1 = __floats2half2_rn(f0.z, f0.w);
            __half2 h2 = __floats2half2_rn(f1.x, f1.y), h3 = __floats2half2_rn(f1.z, f1.w);
            *(uint4*)(smraw + B1A_OFF + off) = make_uint4(*(u32*)&h0, *(u32*)&h1, *(u32*)&h2, *(u32*)&h3);
        }
        {
            float4 f0 = *(const float4*)(Wih1 + wr);
            float4 f1 = *(const float4*)(Wih1 + wr + 4);
            __half2 h0 = __floats2half2_rn(f0.x, f0.y), h1 = __floats2half2_rn(f0.z, f0.w);
            __half2 h2 = __floats2half2_rn(f1.x, f1.y), h3 = __floats2half2_rn(f1.z, f1.w);
            *(uint4*)(smraw + B1B_OFF + off) = make_uint4(*(u32*)&h0, *(u32*)&h1, *(u32*)&h2, *(u32*)&h3);
        }
    }
    __syncthreads();

    // B ldsm_x4 lane mapping: 4 matrices = (tile0,kh0),(tile0,kh1),(tile1,kh0),(tile1,kh1)
    const int bg   = lane >> 3;                 // matrix group 0..3
    const int blr  = lane & 7;
    const int brow = ((bg >> 1) << 3) + blr;    // tile (bg>>1), row blr
    const int btsel = bg & 1;
    const u32 b0_lane  = b0_base  + brow * 1024;
    const u32 b1a_lane = b1a_base + brow * 1024;
    const u32 b1b_lane = b1b_base + brow * 1024;

    // A ldsm lane mapping
    const int arow = mt * 16 + ((lane >> 3) & 1) * 8 + (lane & 7);
    const int at16 = (lane >> 4) & 1;
    const int as   = arow & 7;
    const u32 a0_lane = hs0_base + arow * 1024;
    const u32 a1_lane = hs1_base + arow * 1024;

    // cell mapping (tid < 256)
    const int cm = tid >> 2, cj = tid & 3;
    const int col = blk * 4 + cj;
    float creg0 = 0.f, creg1 = 0.f;
    float b1g0 = 0.f, b1g1 = 0.f, b1g2 = 0.f, b1g3 = 0.f;
    if (tid < 256) {
        b1g0 = bih1[0 * HH + col] + bhh1[0 * HH + col];
        b1g1 = bih1[1 * HH + col] + bhh1[1 * HH + col];
        b1g2 = bih1[2 * HH + col] + bhh1[2 * HH + col];
        b1g3 = bih1[3 * HH + col] + bhh1[3 * HH + col];
    }

    // C fragment coords; partial buffers for this kh (pitch 20)
    const int crow = mt * 16 + (lane >> 2);
    const int cc   = 2 * (lane & 3);
    float* g0p = gates0 + kh * (64 * 20);
    float* g1p = gates1 + kh * (64 * 20);

    #pragma unroll 1
    for (int i = 0; i <= TT; ++i) {
        // prefetch xg for layer0 cell
        float x0 = 0.f, x1 = 0.f, x2 = 0.f, x3 = 0.f;
        if (tid < 256 && i < TT) {
            const float* xp = xg + ((size_t)i * BB + cm) * GG + blk * 16 + cj;
            x0 = xp[0]; x1 = xp[4]; x2 = xp[8]; x3 = xp[12];
        }

        // ---- stage Hs0 = h0[i-1], Hs1 = h1[i-2] ----
        if (i == 0) {
            #pragma unroll
            for (int r = 0; r < 8; ++r) {
                int e = r * 512 + tid;
                int row = e >> 6, sc = e & 63;
                u32 off = row * 1024 + ((u32)(sc ^ (row & 7))) * 16;
                *(uint4*)(smraw + HS0_OFF + off) = make_uint4(0u, 0u, 0u, 0u);
                *(uint4*)(smraw + HS1_OFF + off) = make_uint4(0u, 0u, 0u, 0u);
            }
        } else {
            const __half* hp0 = h016 + (size_t)(i - 1) * BB * HH;
            #pragma unroll
            for (int r = 0; r < 8; ++r) {
                int e = r * 512 + tid;
                int row = e >> 6, sc = e & 63;
                uint4 v = *(const uint4*)(hp0 + (size_t)row * HH + sc * 8);
                u32 off = row * 1024 + ((u32)(sc ^ (row & 7))) * 16;
                *(uint4*)(smraw + HS0_OFF + off) = v;
            }
            if (i == 1) {
                #pragma unroll
                for (int r = 0; r < 8; ++r) {
                    int e = r * 512 + tid;
                    int row = e >> 6, sc = e & 63;
                    u32 off = row * 1024 + ((u32)(sc ^ (row & 7))) * 16;
                    *(uint4*)(smraw + HS1_OFF + off) = make_uint4(0u, 0u, 0u, 0u);
                }
            } else {
                const __half* hp1 = h116 + (size_t)(i - 2) * BB * HH;
                #pragma unroll
                for (int r = 0; r < 8; ++r) {
                    int e = r * 512 + tid;
                    int row = e >> 6, sc = e & 63;
                    uint4 v = *(const uint4*)(hp1 + (size_t)row * HH + sc * 8);
                    u32 off = row * 1024 + ((u32)(sc ^ (row & 7))) * 16;
                    *(uint4*)(smraw + HS1_OFF + off) = v;
                }
            }
        }
        __syncthreads();

        // ---- MMA: fused A0 pass (layer0 B0 + layer1 B1B), then A1 pass (B1A) ----
        float c00 = 0.f, c01 = 0.f, c02 = 0.f, c03 = 0.f;
        float c10 = 0.f, c11 = 0.f, c12 = 0.f, c13 = 0.f;
        float d00 = 0.f, d01 = 0.f, d02 = 0.f, d03 = 0.f;
        float d10 = 0.f, d11 = 0.f, d12 = 0.f, d13 = 0.f;
        #pragma unroll
        for (int j = 0; j < 8; ++j) {
            int kt = kh * 8 + j;
            u32 ch  = (u32)((2 * kt + at16) ^ as);
            u32 bch = (u32)((2 * kt + btsel) ^ blr);
            u32 a0, a1, a2, a3, p0, p1, p2, p3;
            ldsm_x4(a0, a1, a2, a3, a0_lane + ch * 16);
            ldsm_x4(p0, p1, p2, p3, b0_lane + bch * 16);
            mma16816(c00, c01, c02, c03, a0, a1, a2, a3, p0, p1);
            mma16816(c10, c11, c12, c13, a0, a1, a2, a3, p2, p3);
            ldsm_x4(p0, p1, p2, p3, b1b_lane + bch * 16);
            mma16816(d00, d01, d02, d03, a0, a1, a2, a3, p0, p1);
            mma16816(d10, d11, d12, d13, a0, a1, a2, a3, p2, p3);
        }
        #pragma unroll
        for (int j = 0; j < 8; ++j) {
            int kt = kh * 8 + j;
            u32 ch  = (u32)((2 * kt + at16) ^ as);
            u32 bch = (u32)((2 * kt + btsel) ^ blr);
            u32 a0, a1, a2, a3, p0, p1, p2, p3;
            ldsm_x4(a0, a1, a2, a3, a1_lane + ch * 16);
            ldsm_x4(p0, p1, p2, p3, b1a_lane + bch * 16);
            mma16816(d00, d01, d02, d03, a0, a1, a2, a3, p0, p1);
            mma16816(d10, d11, d12, d13, a0, a1, a2, a3, p2, p3);
        }
        *(float2*)&g0p[crow * 20 + cc]           = make_float2(c00, c01);
        *(float2*)&g0p[(crow + 8) * 20 + cc]     = make_float2(c02, c03);
        *(float2*)&g0p[crow * 20 + 8 + cc]       = make_float2(c10, c11);
        *(float2*)&g0p[(crow + 8) * 20 + 8 + cc] = make_float2(c12, c13);
        *(float2*)&g1p[crow * 20 + cc]           = make_float2(d00, d01);
        *(float2*)&g1p[(crow + 8) * 20 + cc]     = make_float2(d02, d03);
        *(float2*)&g1p[crow * 20 + 8 + cc]       = make_float2(d10, d11);
        *(float2*)&g1p[(crow + 8) * 20 + 8 + cc] = make_float2(d12, d13);
        __syncthreads();

        // ---- cells (tid < 256): float4 reduce over 4 kh-partials ----
        if (tid < 256) {
            if (i < TT) {
                const float* gp = gates0 + cm * 20 + 4 * cj;
                float4 v0 = *(const float4*)(gp);
                float4 v1 = *(const float4*)(gp + 1280);
                float4 v2 = *(const float4*)(gp + 2560);
                float4 v3 = *(const float4*)(gp + 3840);
                float s0 = v0.x + v1.x + v2.x + v3.x;
                float s1 = v0.y + v1.y + v2.y + v3.y;
                float s2 = v0.z + v1.z + v2.z + v3.z;
                float s3 = v0.w + v1.w + v2.w + v3.w;
                float gi_ = sigf (s0 + x0);
                float gf_ = sigf (s1 + x1);
                float gz_ = tanhf(s2 + x2);
                float go_ = sigf (s3 + x3);
                creg0 = gf_ * creg0 + gi_ * gz_;
                float h = go_ * tanhf(creg0);
                h016[((size_t)i * BB + cm) * HH + col] = __float2half(h);
            }
            if (i >= 1) {
                const float* gp = gates1 + cm * 20 + 4 * cj;
                float4 v0 = *(const float4*)(gp);
                float4 v1 = *(const float4*)(gp + 1280);
                float4 v2 = *(const float4*)(gp + 2560);
                float4 v3 = *(const float4*)(gp + 3840);
                float s0 = v0.x + v1.x + v2.x + v3.x;
                float s1 = v0.y + v1.y + v2.y + v3.y;
                float s2 = v0.z + v1.z + v2.z + v3.z;
                float s3 = v0.w + v1.w + v2.w + v3.w;
                float gi_ = sigf (s0 + b1g0);
                float gf_ = sigf (s1 + b1g1);
                float gz_ = tanhf(s2 + b1g2);
                float go_ = sigf (s3 + b1g3);
                creg1 = gf_ * creg1 + gi_ * gz_;
                float h = go_ * tanhf(creg1);
                h116[((size_t)(i - 1) * BB + cm) * HH + col] = __float2half(h);
                if (i == TT) finalout[(size_t)cm * HH + col] = h;
            }
        }

        // ---- grid barrier: single counter, leader poll ----
        if (i < TT) {
            __syncthreads();
            if (tid == 0) {
                red_release_add(cnt, 1u);
                u32 target = (u32)NBLK * (u32)(i + 1);
                while (ld_acquire(cnt) < target) {}
            }
            __syncthreads();
        }
    }
}

// ---------------- launch ----------------
extern "C" void kernel_launch(void* const* d_in, const int* in_sizes, int n_in,
                              void* d_out, int out_size) {
    const float* x    = (const float*)d_in[0];
    const float* Wih0 = (const float*)d_in[1];
    const float* Whh0 = (const float*)d_in[2];
    const float* bih0 = (const float*)d_in[3];
    const float* bhh0 = (const float*)d_in[4];
    const float* Wih1 = (const float*)d_in[5];
    const float* Whh1 = (const float*)d_in[6];
    const float* bih1 = (const float*)d_in[7];
    const float* bhh1 = (const float*)d_in[8];
    float* out = (float*)d_out;

    float* xg;
    __half *xh, *h016, *h116;
    u32* cnt;
    cudaGetSymbolAddress((void**)&xh,   g_xh);
    cudaGetSymbolAddress((void**)&xg,   g_xg);
    cudaGetSymbolAddress((void**)&h016, g_h016);
    cudaGetSymbolAddress((void**)&h116, g_h116);
    cudaGetSymbolAddress((void**)&cnt,  g_cnt);

    cudaFuncSetAttribute(lstm_fused, cudaFuncAttributeMaxDynamicSharedMemorySize, SMEM_TOTAL);
    cudaFuncSetAttribute(gemm_gates_hmma, cudaFuncAttributeMaxDynamicSharedMemorySize, GSM_TOTAL);

    reset_kernel<<<1, 32>>>();

    dim3 tb(32, 8), tg(TT / 32, FF / 32, BB);
    transpose_x_kernel<<<tg, tb>>>(x);

    gemm_gates_hmma<<<dim3(GG / 64, TT * BB / 128), 256, GSM_TOTAL>>>(xh, Wih0, bih0, bhh0, xg);
    lstm_fused<<<NBLK, 512, SMEM_TOTAL>>>(xg, Whh0, Whh1, Wih1, bih1, bhh1,
                                          h016, h116, out, cnt);
}

// round 14
// speedup vs baseline: 4.8938x; 1.2982x over previous
#include <cuda_runtime.h>
#include <cuda_fp16.h>
#include <math.h>

#define BB 64
#define FF 128
#define TT 1024
#define HH 512
#define GG 2048
#define NBLK 128

typedef unsigned long long ull;
typedef unsigned int u32;

// ---------------- device globals (no allocation allowed) ----------------
__device__ __half  g_xh  [(size_t)TT * BB * FF];   // (T*B, F) f16
__device__ float   g_xg  [(size_t)TT * BB * GG];   // layer0 gate preacts (permuted layout)
__device__ __half  g_h016[(size_t)TT * BB * HH];   // layer0 h f16 [t][m][k]
__device__ __half  g_h116[(size_t)TT * BB * HH];   // layer1 h f16 [s][m][k]
__device__ u32     g_cnt;                          // barrier counter

// ---------------- helpers ----------------
__device__ __forceinline__ float sigf(float x) { return 1.f / (1.f + __expf(-x)); }

__device__ __forceinline__ void red_release_add(u32* p, u32 v) {
    asm volatile("red.release.gpu.global.add.u32 [%0], %1;" :: "l"(p), "r"(v) : "memory");
}
__device__ __forceinline__ u32 ld_acquire(const u32* p) {
    u32 v;
    asm volatile("ld.acquire.gpu.global.u32 %0, [%1];" : "=r"(v) : "l"(p) : "memory");
    return v;
}
__device__ __forceinline__ u32 smem_u32(const void* p) {
    u32 a;
    asm("{ .reg .u64 t; cvta.to.shared.u64 t, %1; cvt.u32.u64 %0, t; }" : "=r"(a) : "l"(p));
    return a;
}
__device__ __forceinline__ void cp_async16(u32 saddr, const void* gptr) {
    asm volatile("cp.async.cg.shared.global [%0], [%1], 16;" :: "r"(saddr), "l"(gptr) : "memory");
}
__device__ __forceinline__ void cp_commit_wait() {
    asm volatile("cp.async.commit_group;" ::: "memory");
    asm volatile("cp.async.wait_group 0;" ::: "memory");
}
__device__ __forceinline__ void ldsm_x4(u32& r0, u32& r1, u32& r2, u32& r3, u32 addr) {
    asm volatile("ldmatrix.sync.aligned.m8n8.x4.shared.b16 {%0,%1,%2,%3}, [%4];"
                 : "=r"(r0), "=r"(r1), "=r"(r2), "=r"(r3) : "r"(addr));
}
__device__ __forceinline__ void ldsm_x2(u32& r0, u32& r1, u32 addr) {
    asm volatile("ldmatrix.sync.aligned.m8n8.x2.shared.b16 {%0,%1}, [%2];"
                 : "=r"(r0), "=r"(r1) : "r"(addr));
}
__device__ __forceinline__ void mma16816(float& c0, float& c1, float& c2, float& c3,
                                         u32 a0, u32 a1, u32 a2, u32 a3, u32 b0, u32 b1) {
    asm volatile("mma.sync.aligned.m16n8k16.row.col.f32.f16.f16.f32 "
                 "{%0,%1,%2,%3}, {%4,%5,%6,%7}, {%8,%9}, {%0,%1,%2,%3};"
                 : "+f"(c0), "+f"(c1), "+f"(c2), "+f"(c3)
                 : "r"(a0), "r"(a1), "r"(a2), "r"(a3), "r"(b0), "r"(b1));
}

// ---------------- reset counter ----------------
__global__ void reset_kernel() {
    if (threadIdx.x == 0) g_cnt = 0u;
}

// ---------------- transpose x (B,F,T) f32 -> (T*B, F) f16 ----------------
__global__ void transpose_x_kernel(const float* __restrict__ x) {
    __shared__ float tile[32][33];
    int b  = blockIdx.z;
    int t0 = blockIdx.x * 32;
    int f0 = blockIdx.y * 32;
    for (int i = threadIdx.y; i < 32; i += 8)
        tile[i][threadIdx.x] = x[(size_t)b * FF * TT + (size_t)(f0 + i) * TT + t0 + threadIdx.x];
    __syncthreads();
    for (int i = threadIdx.y; i < 32; i += 8)
        g_xh[((size_t)(t0 + i) * BB + b) * FF + f0 + threadIdx.x] =
            __float2half(tile[threadIdx.x][i]);
}

// ---------------- layer0 input GEMM (HMMA): xg = xh(M,128) @ Wih0^T + b ----------------
#define GA_OFF 0
#define GB_OFF 32768
#define GSM_TOTAL (32768 + 16384)
__global__ __launch_bounds__(256, 3)
void gemm_gates_hmma(const __half* __restrict__ Ah, const float* __restrict__ W,
                     const float* __restrict__ bih, const float* __restrict__ bhh,
                     float* __restrict__ C) {
    extern __shared__ __align__(16) char gsm[];
    const u32 asm_base = smem_u32(gsm + GA_OFF);
    const u32 bsm_base = smem_u32(gsm + GB_OFF);
    const int tid = threadIdx.x;
    const int wid = tid >> 5, lane = tid & 31;
    const int n0 = blockIdx.x * 64;
    const int m0 = blockIdx.y * 128;

    #pragma unroll
    for (int i = 0; i < 8; ++i) {
        int e = i * 256 + tid;
        int row = e >> 4, ch = e & 15;
        uint4 v = *(const uint4*)(Ah + ((size_t)(m0 + row)) * FF + ch * 8);
        *(uint4*)(gsm + GA_OFF + row * 256 + ((u32)(ch ^ (row & 7))) * 16) = v;
    }
    #pragma unroll
    for (int i = 0; i < 4; ++i) {
        int e = i * 256 + tid;
        int row = e >> 4, ch = e & 15;
        const float* wsrc = W + (size_t)(n0 + row) * FF + ch * 8;
        float4 f0 = *(const float4*)wsrc;
        float4 f1 = *(const float4*)(wsrc + 4);
        __half2 h0 = __floats2half2_rn(f0.x, f0.y), h1 = __floats2half2_rn(f0.z, f0.w);
        __half2 h2 = __floats2half2_rn(f1.x, f1.y), h3 = __floats2half2_rn(f1.z, f1.w);
        *(uint4*)(gsm + GB_OFF + row * 256 + ((u32)(ch ^ (row & 7))) * 16) =
            make_uint4(*(u32*)&h0, *(u32*)&h1, *(u32*)&h2, *(u32*)&h3);
    }
    __syncthreads();

    const int mt = wid;
    const int arow = mt * 16 + ((lane >> 3) & 1) * 8 + (lane & 7);
    const int at16 = (lane >> 4) & 1;
    const int as   = arow & 7;
    const u32 a_lane = asm_base + arow * 256;

    const int al = lane & 15;
    const int brow_l = al & 7;
    const int btsel = (al >> 3) & 1;

    float acc[8][4];
    #pragma unroll
    for (int nt = 0; nt < 8; ++nt)
        #pragma unroll
        for (int p = 0; p < 4; ++p) acc[nt][p] = 0.f;

    #pragma unroll
    for (int kt = 0; kt < 8; ++kt) {
        u32 ch = (u32)((2 * kt + at16) ^ as);
        u32 a0, a1, a2, a3;
        ldsm_x4(a0, a1, a2, a3, a_lane + ch * 16);
        #pragma unroll
        for (int nt = 0; nt < 8; ++nt) {
            int brow = nt * 8 + brow_l;
            u32 bch = (u32)((2 * kt + btsel) ^ (brow & 7));
            u32 b0, b1;
            ldsm_x2(b0, b1, bsm_base + brow * 256 + bch * 16);
            mma16816(acc[nt][0], acc[nt][1], acc[nt][2], acc[nt][3], a0, a1, a2, a3, b0, b1);
        }
    }

    const int crow = mt * 16 + (lane >> 2);
    #pragma unroll
    for (int nt = 0; nt < 8; ++nt) {
        int na = n0 + nt * 8 + 2 * (lane & 3);
        int q = na >> 9, hc = na & 511;
        size_t cb = (size_t)((hc >> 2) << 4) + q * 4 + (hc & 3);
        float ba = bih[na] + bhh[na];
        float bb = bih[na + 1] + bhh[na + 1];
        *(float2*)&C[(size_t)(m0 + crow) * GG + cb] =
            make_float2(acc[nt][0] + ba, acc[nt][1] + bb);
        *(float2*)&C[(size_t)(m0 + crow + 8) * GG + cb] =
            make_float2(acc[nt][2] + ba, acc[nt][3] + bb);
    }
}

// ---------------- fused 2-layer persistent HMMA LSTM (lag-2 skew) ----------------
// Iter i: layer0 computes h0[i] (i<TT); layer1 computes h1[i-2] (i>=2) with
//   gates1 = h1[i-3]@Whh1^T + h0[i-2]@Wih1^T + b1.
// The h0[i-2]@Wih1 pass runs in the tail of iter i-1 (barrier-wait shadow) using
// the Hs0 tile staged there (still = h0[i-2]); result carried in registers.
#define HS0_OFF  0
#define HS1_OFF  65536
#define B0_OFF   131072
#define B1A_OFF  (131072 + 16384)
#define B1B_OFF  (131072 + 32768)
#define GT0_OFF  (131072 + 49152)             // [4][64][20] f32 = 20480B
#define GT1_OFF  (GT0_OFF + 20480)
#define SMEM_TOTAL (GT1_OFF + 20480)

__global__ __launch_bounds__(512, 1)
void lstm_fused(const float* __restrict__ xg,
                const float* __restrict__ Whh0,
                const float* __restrict__ Whh1, const float* __restrict__ Wih1,
                const float* __restrict__ bih1, const float* __restrict__ bhh1,
                __half* __restrict__ h016, __half* __restrict__ h116,
                float* __restrict__ finalout, u32* __restrict__ cnt) {
    extern __shared__ __align__(16) char smraw[];
    const u32 hs0_base = smem_u32(smraw + HS0_OFF);
    const u32 hs1_base = smem_u32(smraw + HS1_OFF);
    const u32 b0_base  = smem_u32(smraw + B0_OFF);
    const u32 b1a_base = smem_u32(smraw + B1A_OFF);
    const u32 b1b_base = smem_u32(smraw + B1B_OFF);
    float* gates0 = (float*)(smraw + GT0_OFF);      // [4][64][20]
    float* gates1 = (float*)(smraw + GT1_OFF);      // [4][64][20]

    const int tid = threadIdx.x, blk = blockIdx.x;
    const int wid = tid >> 5, lane = tid & 31;
    const int mt = wid & 3, kh = wid >> 2;          // kh 0..3 (K quarter)

    // ---- stage the three weight slices (16 x 512 f16 each, swizzled), once ----
    // Staged row n corresponds to weight row (q = n&3)*HH + blk*4 + (j = n>>2).
    for (int e = tid; e < 1024; e += 512) {
        int row = e >> 6, c = e & 63;
        size_t wr = (size_t)((row & 3) * HH + blk * 4 + (row >> 2)) * HH + c * 8;
        u32 off = row * 1024 + ((u32)(c ^ (row & 7))) * 16;
        {
            float4 f0 = *(const float4*)(Whh0 + wr);
            float4 f1 = *(const float4*)(Whh0 + wr + 4);
            __half2 h0 = __floats2half2_rn(f0.x, f0.y), h1 = __floats2half2_rn(f0.z, f0.w);
            __half2 h2 = __floats2half2_rn(f1.x, f1.y), h3 = __floats2half2_rn(f1.z, f1.w);
            *(uint4*)(smraw + B0_OFF + off) = make_uint4(*(u32*)&h0, *(u32*)&h1, *(u32*)&h2, *(u32*)&h3);
        }
        {
            float4 f0 = *(const float4*)(Whh1 + wr);
            float4 f1 = *(const float4*)(Whh1 + wr + 4);
            __half2 h0 = __floats2half2_rn(f0.x, f0.y), h1 = __floats2half2_rn(f0.z, f0.w);
            __half2 h2 = __floats2half2_rn(f1.x, f1.y), h3 = __floats2half2_rn(f1.z, f1.w);
            *(uint4*)(smraw + B1A_OFF + off) = make_uint4(*(u32*)&h0, *(u32*)&h1, *(u32*)&h2, *(u32*)&h3);
        }
        {
            float4 f0 = *(const float4*)(Wih1 + wr);
            float4 f1 = *(const float4*)(Wih1 + wr + 4);
            __half2 h0 = __floats2half2_rn(f0.x, f0.y), h1 = __floats2half2_rn(f0.z, f0.w);
            __half2 h2 = __floats2half2_rn(f1.x, f1.y), h3 = __floats2half2_rn(f1.z, f1.w);
            *(uint4*)(smraw + B1B_OFF + off) = make_uint4(*(u32*)&h0, *(u32*)&h1, *(u32*)&h2, *(u32*)&h3);
        }
    }
    __syncthreads();

    // B ldsm_x4 lane mapping: 4 matrices = (tile0,k0),(tile0,k1),(tile1,k0),(tile1,k1)
    const int bg   = lane >> 3;
    const int blr  = lane & 7;
    const int brow = ((bg >> 1) << 3) + blr;
    const int btsel = bg & 1;
    const u32 b0_lane  = b0_base  + brow * 1024;
    const u32 b1a_lane = b1a_base + brow * 1024;
    const u32 b1b_lane = b1b_base + brow * 1024;

    // A ldsm lane mapping
    const int arow = mt * 16 + ((lane >> 3) & 1) * 8 + (lane & 7);
    const int at16 = (lane >> 4) & 1;
    const int as   = arow & 7;
    const u32 a0_lane = hs0_base + arow * 1024;
    const u32 a1_lane = hs1_base + arow * 1024;

    // cell mapping (tid < 256)
    const int cm = tid >> 2, cj = tid & 3;
    const int col = blk * 4 + cj;
    float creg0 = 0.f, creg1 = 0.f;
    float b1g0 = 0.f, b1g1 = 0.f, b1g2 = 0.f, b1g3 = 0.f;
    if (tid < 256) {
        b1g0 = bih1[0 * HH + col] + bhh1[0 * HH + col];
        b1g1 = bih1[1 * HH + col] + bhh1[1 * HH + col];
        b1g2 = bih1[2 * HH + col] + bhh1[2 * HH + col];
        b1g3 = bih1[3 * HH + col] + bhh1[3 * HH + col];
    }

    // C fragment coords; partial buffers for this kh (pitch 20)
    const int crow = mt * 16 + (lane >> 2);
    const int cc   = 2 * (lane & 3);
    float* g0p = gates0 + kh * (64 * 20);
    float* g1p = gates1 + kh * (64 * 20);

    // carried layer1 partial accumulators (B1B pre-pass result)
    float d00 = 0.f, d01 = 0.f, d02 = 0.f, d03 = 0.f;
    float d10 = 0.f, d11 = 0.f, d12 = 0.f, d13 = 0.f;

    #pragma unroll 1
    for (int i = 0; i <= TT + 1; ++i) {
        // prefetch xg for layer0 cell
        float x0 = 0.f, x1 = 0.f, x2 = 0.f, x3 = 0.f;
        if (tid < 256 && i < TT) {
            const float* xp = xg + ((size_t)i * BB + cm) * GG + blk * 16 + cj;
            x0 = xp[0]; x1 = xp[4]; x2 = xp[8]; x3 = xp[12];
        }

        // ---- stage Hs0 <- h0[i-1] (1<=i<=TT; zero at i==0), Hs1 <- h1[i-3] (i>=3; zero at i==2) ----
        if (i == 0) {
            #pragma unroll
            for (int r = 0; r < 8; ++r) {
                int e = r * 512 + tid;
                int row = e >> 6, sc = e & 63;
                u32 off = row * 1024 + ((u32)(sc ^ (row & 7))) * 16;
                *(uint4*)(smraw + HS0_OFF + off) = make_uint4(0u, 0u, 0u, 0u);
            }
        } else if (i <= TT) {
            const __half* hp0 = h016 + (size_t)(i - 1) * BB * HH;
            #pragma unroll
            for (int r = 0; r < 8; ++r) {
                int e = r * 512 + tid;
                int row = e >> 6, sc = e & 63;
                u32 off = row * 1024 + ((u32)(sc ^ (row & 7))) * 16;
                cp_async16(hs0_base + off, hp0 + (size_t)row * HH + sc * 8);
            }
        }
        if (i == 2) {
            #pragma unroll
            for (int r = 0; r < 8; ++r) {
                int e = r * 512 + tid;
                int row = e >> 6, sc = e & 63;
                u32 off = row * 1024 + ((u32)(sc ^ (row & 7))) * 16;
                *(uint4*)(smraw + HS1_OFF + off) = make_uint4(0u, 0u, 0u, 0u);
            }
        } else if (i >= 3) {
            const __half* hp1 = h116 + (size_t)(i - 3) * BB * HH;
            #pragma unroll
            for (int r = 0; r < 8; ++r) {
                int e = r * 512 + tid;
                int row = e >> 6, sc = e & 63;
                u32 off = row * 1024 + ((u32)(sc ^ (row & 7))) * 16;
                cp_async16(hs1_base + off, hp1 + (size_t)row * HH + sc * 8);
            }
        }
        cp_commit_wait();
        __syncthreads();

        // ---- body MMA ----
        if (i < TT) {   // layer0: c = Hs0 @ B0^T
            float c00 = 0.f, c01 = 0.f, c02 = 0.f, c03 = 0.f;
            float c10 = 0.f, c11 = 0.f, c12 = 0.f, c13 = 0.f;
            #pragma unroll
            for (int j = 0; j < 8; ++j) {
                int kt = kh * 8 + j;
                u32 ch  = (u32)((2 * kt + at16) ^ as);
                u32 bch = (u32)((2 * kt + btsel) ^ blr);
                u32 a0, a1, a2, a3, p0, p1, p2, p3;
                ldsm_x4(a0, a1, a2, a3, a0_lane + ch * 16);
                ldsm_x4(p0, p1, p2, p3, b0_lane + bch * 16);
                mma16816(c00, c01, c02, c03, a0, a1, a2, a3, p0, p1);
                mma16816(c10, c11, c12, c13, a0, a1, a2, a3, p2, p3);
            }
            *(float2*)&g0p[crow * 20 + cc]           = make_float2(c00, c01);
            *(float2*)&g0p[(crow + 8) * 20 + cc]     = make_float2(c02, c03);
            *(float2*)&g0p[crow * 20 + 8 + cc]       = make_float2(c10, c11);
            *(float2*)&g0p[(crow + 8) * 20 + 8 + cc] = make_float2(c12, c13);
        }
        if (i >= 2) {   // layer1: d += Hs1 @ B1A^T (d carries the B1B pre-pass)
            #pragma unroll
            for (int j = 0; j < 8; ++j) {
                int kt = kh * 8 + j;
                u32 ch  = (u32)((2 * kt + at16) ^ as);
                u32 bch = (u32)((2 * kt + btsel) ^ blr);
                u32 a0, a1, a2, a3, p0, p1, p2, p3;
                ldsm_x4(a0, a1, a2, a3, a1_lane + ch * 16);
                ldsm_x4(p0, p1, p2, p3, b1a_lane + bch * 16);
                mma16816(d00, d01, d02, d03, a0, a1, a2, a3, p0, p1);
                mma16816(d10, d11, d12, d13, a0, a1, a2, a3, p2, p3);
            }
            *(float2*)&g1p[crow * 20 + cc]           = make_float2(d00, d01);
            *(float2*)&g1p[(crow + 8) * 20 + cc]     = make_float2(d02, d03);
            *(float2*)&g1p[crow * 20 + 8 + cc]       = make_float2(d10, d11);
            *(float2*)&g1p[(crow + 8) * 20 + 8 + cc] = make_float2(d12, d13);
        }
        __syncthreads();

        // ---- cells (tid < 256) ----
        if (tid < 256) {
            if (i < TT) {
                const float* gp = gates0 + cm * 20 + 4 * cj;
                float4 v0 = *(const float4*)(gp);
                float4 v1 = *(const float4*)(gp + 1280);
                float4 v2 = *(const float4*)(gp + 2560);
                float4 v3 = *(const float4*)(gp + 3840);
                float s0 = v0.x + v1.x + v2.x + v3.x;
                float s1 = v0.y + v1.y + v2.y + v3.y;
                float s2 = v0.z + v1.z + v2.z + v3.z;
                float s3 = v0.w + v1.w + v2.w + v3.w;
                float gi_ = sigf (s0 + x0);
                float gf_ = sigf (s1 + x1);
                float gz_ = tanhf(s2 + x2);
                float go_ = sigf (s3 + x3);
                creg0 = gf_ * creg0 + gi_ * gz_;
                float h = go_ * tanhf(creg0);
                h016[((size_t)i * BB + cm) * HH + col] = __float2half(h);
            }
            if (i >= 2) {
                const float* gp = gates1 + cm * 20 + 4 * cj;
                float4 v0 = *(const float4*)(gp);
                float4 v1 = *(const float4*)(gp + 1280);
                float4 v2 = *(const float4*)(gp + 2560);
                float4 v3 = *(const float4*)(gp + 3840);
                float s0 = v0.x + v1.x + v2.x + v3.x;
                float s1 = v0.y + v1.y + v2.y + v3.y;
                float s2 = v0.z + v1.z + v2.z + v3.z;
                float s3 = v0.w + v1.w + v2.w + v3.w;
                float gi_ = sigf (s0 + b1g0);
                float gf_ = sigf (s1 + b1g1);
                float gz_ = tanhf(s2 + b1g2);
                float go_ = sigf (s3 + b1g3);
                creg1 = gf_ * creg1 + gi_ * gz_;
                float h = go_ * tanhf(creg1);
                h116[((size_t)(i - 2) * BB + cm) * HH + col] = __float2half(h);
                if (i == TT + 1) finalout[(size_t)cm * HH + col] = h;
            }
        }

        // ---- tail: arrive early, B1B pre-pass in barrier shadow, poll ----
        if (i <= TT) {
            __syncthreads();
            if (tid == 0) red_release_add(cnt, 1u);
            // d = Hs0(h0[i-1]) @ B1B^T  (operand for iter i+1's layer1)
            d00 = 0.f; d01 = 0.f; d02 = 0.f; d03 = 0.f;
            d10 = 0.f; d11 = 0.f; d12 = 0.f; d13 = 0.f;
            if (i >= 1) {
                #pragma unroll
                for (int j = 0; j < 8; ++j) {
                    int kt = kh * 8 + j;
                    u32 ch  = (u32)((2 * kt + at16) ^ as);
                    u32 bch = (u32)((2 * kt + btsel) ^ blr);
                    u32 a0, a1, a2, a3, p0, p1, p2, p3;
                    ldsm_x4(a0, a1, a2, a3, a0_lane + ch * 16);
                    ldsm_x4(p0, p1, p2, p3, b1b_lane + bch * 16);
                    mma16816(d00, d01, d02, d03, a0, a1, a2, a3, p0, p1);
                    mma16816(d10, d11, d12, d13, a0, a1, a2, a3, p2, p3);
                }
            }
            if (tid == 0) {
                u32 target = (u32)NBLK * (u32)(i + 1);
                while (ld_acquire(cnt) < target) {}
            }
            __syncthreads();
        }
    }
}

// ---------------- launch ----------------
extern "C" void kernel_launch(void* const* d_in, const int* in_sizes, int n_in,
                              void* d_out, int out_size) {
    const float* x    = (const float*)d_in[0];
    const float* Wih0 = (const float*)d_in[1];
    const float* Whh0 = (const float*)d_in[2];
    const float* bih0 = (const float*)d_in[3];
    const float* bhh0 = (const float*)d_in[4];
    const float* Wih1 = (const float*)d_in[5];
    const float* Whh1 = (const float*)d_in[6];
    const float* bih1 = (const float*)d_in[7];
    const float* bhh1 = (const float*)d_in[8];
    float* out = (float*)d_out;

    float* xg;
    __half *xh, *h016, *h116;
    u32* cnt;
    cudaGetSymbolAddress((void**)&xh,   g_xh);
    cudaGetSymbolAddress((void**)&xg,   g_xg);
    cudaGetSymbolAddress((void**)&h016, g_h016);
    cudaGetSymbolAddress((void**)&h116, g_h116);
    cudaGetSymbolAddress((void**)&cnt,  g_cnt);

    cudaFuncSetAttribute(lstm_fused, cudaFuncAttributeMaxDynamicSharedMemorySize, SMEM_TOTAL);
    cudaFuncSetAttribute(gemm_gates_hmma, cudaFuncAttributeMaxDynamicSharedMemorySize, GSM_TOTAL);

    reset_kernel<<<1, 32>>>();

    dim3 tb(32, 8), tg(TT / 32, FF / 32, BB);
    transpose_x_kernel<<<tg, tb>>>(x);

    gemm_gates_hmma<<<dim3(GG / 64, TT * BB / 128), 256, GSM_TOTAL>>>(xh, Wih0, bih0, bhh0, xg);
    lstm_fused<<<NBLK, 512, SMEM_TOTAL>>>(xg, Whh0, Whh1, Wih1, bih1, bhh1,
                                          h016, h116, out, cnt);
}

// round 15
// speedup vs baseline: 5.6769x; 1.1600x over previous
#include <cuda_runtime.h>
#include <cuda_fp16.h>
#include <math.h>

#define BB 64
#define FF 128
#define TT 1024
#define HH 512
#define GG 2048
#define NBLK 128

typedef unsigned long long ull;
typedef unsigned int u32;

// ---------------- device globals (no allocation allowed) ----------------
__device__ __half  g_xh  [(size_t)TT * BB * FF];   // (T*B, F) f16
__device__ float   g_xg  [(size_t)TT * BB * GG];   // layer0 gate preacts (permuted layout)
__device__ __half  g_h016[(size_t)TT * BB * HH];   // layer0 h f16 [t][m][k]
__device__ __half  g_h116[(size_t)TT * BB * HH];   // layer1 h f16 [s][m][k]
__device__ u32     g_cnt;                          // barrier counter

// ---------------- helpers ----------------
__device__ __forceinline__ float sigf(float x) { return 1.f / (1.f + __expf(-x)); }

__device__ __forceinline__ void red_release_add(u32* p, u32 v) {
    asm volatile("red.release.gpu.global.add.u32 [%0], %1;" :: "l"(p), "r"(v) : "memory");
}
__device__ __forceinline__ u32 ld_acquire(const u32* p) {
    u32 v;
    asm volatile("ld.acquire.gpu.global.u32 %0, [%1];" : "=r"(v) : "l"(p) : "memory");
    return v;
}
__device__ __forceinline__ u32 smem_u32(const void* p) {
    u32 a;
    asm("{ .reg .u64 t; cvta.to.shared.u64 t, %1; cvt.u32.u64 %0, t; }" : "=r"(a) : "l"(p));
    return a;
}
__device__ __forceinline__ void cp_async16(u32 saddr, const void* gptr) {
    asm volatile("cp.async.cg.shared.global [%0], [%1], 16;" :: "r"(saddr), "l"(gptr) : "memory");
}
__device__ __forceinline__ void cp_commit_wait() {
    asm volatile("cp.async.commit_group;" ::: "memory");
    asm volatile("cp.async.wait_group 0;" ::: "memory");
}
__device__ __forceinline__ void ldsm_x4(u32& r0, u32& r1, u32& r2, u32& r3, u32 addr) {
    asm volatile("ldmatrix.sync.aligned.m8n8.x4.shared.b16 {%0,%1,%2,%3}, [%4];"
                 : "=r"(r0), "=r"(r1), "=r"(r2), "=r"(r3) : "r"(addr));
}
__device__ __forceinline__ void mma16816(float& c0, float& c1, float& c2, float& c3,
                                         u32 a0, u32 a1, u32 a2, u32 a3, u32 b0, u32 b1) {
    asm volatile("mma.sync.aligned.m16n8k16.row.col.f32.f16.f16.f32 "
                 "{%0,%1,%2,%3}, {%4,%5,%6,%7}, {%8,%9}, {%0,%1,%2,%3};"
                 : "+f"(c0), "+f"(c1), "+f"(c2), "+f"(c3)
                 : "r"(a0), "r"(a1), "r"(a2), "r"(a3), "r"(b0), "r"(b1));
}

// ---------------- reset counter ----------------
__global__ void reset_kernel() {
    if (threadIdx.x == 0) g_cnt = 0u;
}

// ---------------- transpose x (B,F,T) f32 -> (T*B, F) f16 ----------------
__global__ void transpose_x_kernel(const float* __restrict__ x) {
    __shared__ float tile[32][33];
    int b  = blockIdx.z;
    int t0 = blockIdx.x * 32;
    int f0 = blockIdx.y * 32;
    for (int i = threadIdx.y; i < 32; i += 8)
        tile[i][threadIdx.x] = x[(size_t)b * FF * TT + (size_t)(f0 + i) * TT + t0 + threadIdx.x];
    __syncthreads();
    for (int i = threadIdx.y; i < 32; i += 8)
        g_xh[((size_t)(t0 + i) * BB + b) * FF + f0 + threadIdx.x] =
            __float2half(tile[threadIdx.x][i]);
}

// ---------------- layer0 input GEMM (HMMA): xg = xh(M,128) @ Wih0^T + b ----------------
#define GA_OFF 0
#define GB_OFF 32768
#define GSM_TOTAL (32768 + 16384)
__global__ __launch_bounds__(256, 3)
void gemm_gates_hmma(const __half* __restrict__ Ah, const float* __restrict__ W,
                     const float* __restrict__ bih, const float* __restrict__ bhh,
                     float* __restrict__ C) {
    extern __shared__ __align__(16) char gsm[];
    const u32 asm_base = smem_u32(gsm + GA_OFF);
    const u32 bsm_base = smem_u32(gsm + GB_OFF);
    const int tid = threadIdx.x;
    const int wid = tid >> 5, lane = tid & 31;
    const int n0 = blockIdx.x * 64;
    const int m0 = blockIdx.y * 128;

    #pragma unroll
    for (int i = 0; i < 8; ++i) {
        int e = i * 256 + tid;
        int row = e >> 4, ch = e & 15;
        uint4 v = *(const uint4*)(Ah + ((size_t)(m0 + row)) * FF + ch * 8);
        *(uint4*)(gsm + GA_OFF + row * 256 + ((u32)(ch ^ (row & 7))) * 16) = v;
    }
    #pragma unroll
    for (int i = 0; i < 4; ++i) {
        int e = i * 256 + tid;
        int row = e >> 4, ch = e & 15;
        const float* wsrc = W + (size_t)(n0 + row) * FF + ch * 8;
        float4 f0 = *(const float4*)wsrc;
        float4 f1 = *(const float4*)(wsrc + 4);
        __half2 h0 = __floats2half2_rn(f0.x, f0.y), h1 = __floats2half2_rn(f0.z, f0.w);
        __half2 h2 = __floats2half2_rn(f1.x, f1.y), h3 = __floats2half2_rn(f1.z, f1.w);
        *(uint4*)(gsm + GB_OFF + row * 256 + ((u32)(ch ^ (row & 7))) * 16) =
            make_uint4(*(u32*)&h0, *(u32*)&h1, *(u32*)&h2, *(u32*)&h3);
    }
    __syncthreads();

    const int mt = wid;
    const int arow = mt * 16 + ((lane >> 3) & 1) * 8 + (lane & 7);
    const int at16 = (lane >> 4) & 1;
    const int as   = arow & 7;
    const u32 a_lane = asm_base + arow * 256;

    const int al = lane & 15;
    const int brow_l = al & 7;
    const int btsel = (al >> 3) & 1;

    float acc[8][4];
    #pragma unroll
    for (int nt = 0; nt < 8; ++nt)
        #pragma unroll
        for (int p = 0; p < 4; ++p) acc[nt][p] = 0.f;

    #pragma unroll
    for (int kt = 0; kt < 8; ++kt) {
        u32 ch = (u32)((2 * kt + at16) ^ as);
        u32 a0, a1, a2, a3;
        ldsm_x4(a0, a1, a2, a3, a_lane + ch * 16);
        #pragma unroll
        for (int nt = 0; nt < 8; ++nt) {
            int brow = nt * 8 + brow_l;
            u32 bch = (u32)((2 * kt + btsel) ^ (brow & 7));
            u32 b0, b1;
            asm volatile("ldmatrix.sync.aligned.m8n8.x2.shared.b16 {%0,%1}, [%2];"
                         : "=r"(b0), "=r"(b1) : "r"(bsm_base + brow * 256 + bch * 16));
            mma16816(acc[nt][0], acc[nt][1], acc[nt][2], acc[nt][3], a0, a1, a2, a3, b0, b1);
        }
    }

    const int crow = mt * 16 + (lane >> 2);
    #pragma unroll
    for (int nt = 0; nt < 8; ++nt) {
        int na = n0 + nt * 8 + 2 * (lane & 3);
        int q = na >> 9, hc = na & 511;
        size_t cb = (size_t)((hc >> 2) << 4) + q * 4 + (hc & 3);
        float ba = bih[na] + bhh[na];
        float bb = bih[na + 1] + bhh[na + 1];
        *(float2*)&C[(size_t)(m0 + crow) * GG + cb] =
            make_float2(acc[nt][0] + ba, acc[nt][1] + bb);
        *(float2*)&C[(size_t)(m0 + crow + 8) * GG + cb] =
            make_float2(acc[nt][2] + ba, acc[nt][3] + bb);
    }
}

// ---------------- fused 2-layer persistent HMMA LSTM (lag-2 skew, pinned B) ----------------
// 256 threads / 8 warps, warp = (mt 0..3, kh2 0..1): m16 x n16 x half-K.
// B0 (Whh0) and B1A (Whh1) fragments pinned in registers (loaded once).
// B1B (Wih1) stays in SMEM for the barrier-shadow pre-pass.
#define HS0_OFF  0
#define HS1_OFF  65536
#define B1B_OFF  131072
#define GT0_OFF  (131072 + 16384)             // [2][64][20] f32 = 10240B
#define GT1_OFF  (GT0_OFF + 10240)
#define SMEM_TOTAL (GT1_OFF + 10240)

__global__ __launch_bounds__(256, 1)
void lstm_fused(const float* __restrict__ xg,
                const float* __restrict__ Whh0,
                const float* __restrict__ Whh1, const float* __restrict__ Wih1,
                const float* __restrict__ bih1, const float* __restrict__ bhh1,
                __half* __restrict__ h016, __half* __restrict__ h116,
                float* __restrict__ finalout, u32* __restrict__ cnt) {
    extern __shared__ __align__(16) char smraw[];
    const u32 hs0_base = smem_u32(smraw + HS0_OFF);
    const u32 hs1_base = smem_u32(smraw + HS1_OFF);
    const u32 b1b_base = smem_u32(smraw + B1B_OFF);
    float* gates0 = (float*)(smraw + GT0_OFF);      // [2][64][20]
    float* gates1 = (float*)(smraw + GT1_OFF);      // [2][64][20]

    const int tid = threadIdx.x, blk = blockIdx.x;
    const int wid = tid >> 5, lane = tid & 31;
    const int mt = wid & 3, kh2 = wid >> 2;         // kh2 0..1 (K half)

    // ---- stage weight slices: Whh0 -> HS0+0, Whh1 -> HS0+16K (temps), Wih1 -> B1B ----
    // Staged row n = j*4+q corresponds to weight row q*HH + blk*4 + j.
    for (int e = tid; e < 1024; e += 256) {
        int row = e >> 6, c = e & 63;
        size_t wr = (size_t)((row & 3) * HH + blk * 4 + (row >> 2)) * HH + c * 8;
        u32 off = row * 1024 + ((u32)(c ^ (row & 7))) * 16;
        {
            float4 f0 = *(const float4*)(Whh0 + wr);
            float4 f1 = *(const float4*)(Whh0 + wr + 4);
            __half2 h0 = __floats2half2_rn(f0.x, f0.y), h1 = __floats2half2_rn(f0.z, f0.w);
            __half2 h2 = __floats2half2_rn(f1.x, f1.y), h3 = __floats2half2_rn(f1.z, f1.w);
            *(uint4*)(smraw + off) = make_uint4(*(u32*)&h0, *(u32*)&h1, *(u32*)&h2, *(u32*)&h3);
        }
        {
            float4 f0 = *(const float4*)(Whh1 + wr);
            float4 f1 = *(const float4*)(Whh1 + wr + 4);
            __half2 h0 = __floats2half2_rn(f0.x, f0.y), h1 = __floats2half2_rn(f0.z, f0.w);
            __half2 h2 = __floats2half2_rn(f1.x, f1.y), h3 = __floats2half2_rn(f1.z, f1.w);
            *(uint4*)(smraw + 16384 + off) = make_uint4(*(u32*)&h0, *(u32*)&h1, *(u32*)&h2, *(u32*)&h3);
        }
        {
            float4 f0 = *(const float4*)(Wih1 + wr);
            float4 f1 = *(const float4*)(Wih1 + wr + 4);
            __half2 h0 = __floats2half2_rn(f0.x, f0.y), h1 = __floats2half2_rn(f0.z, f0.w);
            __half2 h2 = __floats2half2_rn(f1.x, f1.y), h3 = __floats2half2_rn(f1.z, f1.w);
            *(uint4*)(smraw + B1B_OFF + off) = make_uint4(*(u32*)&h0, *(u32*)&h1, *(u32*)&h2, *(u32*)&h3);
        }
    }
    __syncthreads();

    // B ldsm_x4 lane mapping: 4 matrices = (tile0,k0),(tile0,k1),(tile1,k0),(tile1,k1)
    const int bg   = lane >> 3;
    const int blr  = lane & 7;
    const int brow = ((bg >> 1) << 3) + blr;
    const int btsel = bg & 1;

    // ---- pin B0 (Whh0) and B1A (Whh1) fragments: 16 ktiles x 4 regs each ----
    u32 b0f[64], b1af[64];
    #pragma unroll
    for (int j = 0; j < 16; ++j) {
        int kt = kh2 * 16 + j;
        u32 bch = (u32)(((2 * kt + btsel) ^ blr)) * 16;
        ldsm_x4(b0f[4 * j], b0f[4 * j + 1], b0f[4 * j + 2], b0f[4 * j + 3],
                hs0_base + brow * 1024 + bch);
        ldsm_x4(b1af[4 * j], b1af[4 * j + 1], b1af[4 * j + 2], b1af[4 * j + 3],
                hs0_base + 16384 + brow * 1024 + bch);
    }
    __syncthreads();

    const u32 b1b_lane = b1b_base + brow * 1024;

    // A ldsm lane mapping
    const int arow = mt * 16 + ((lane >> 3) & 1) * 8 + (lane & 7);
    const int at16 = (lane >> 4) & 1;
    const int as   = arow & 7;
    const u32 a0_lane = hs0_base + arow * 1024;
    const u32 a1_lane = hs1_base + arow * 1024;

    // cell mapping (all 256 threads)
    const int cm = tid >> 2, cj = tid & 3;
    const int col = blk * 4 + cj;
    float creg0 = 0.f, creg1 = 0.f;
    float b1g0 = bih1[0 * HH + col] + bhh1[0 * HH + col];
    float b1g1 = bih1[1 * HH + col] + bhh1[1 * HH + col];
    float b1g2 = bih1[2 * HH + col] + bhh1[2 * HH + col];
    float b1g3 = bih1[3 * HH + col] + bhh1[3 * HH + col];

    // C fragment coords; partial buffers for this kh2 (pitch 20)
    const int crow = mt * 16 + (lane >> 2);
    const int cc   = 2 * (lane & 3);
    float* g0p = gates0 + kh2 * (64 * 20);
    float* g1p = gates1 + kh2 * (64 * 20);

    // carried layer1 partial accumulators (B1B shadow pre-pass result)
    float d00 = 0.f, d01 = 0.f, d02 = 0.f, d03 = 0.f;
    float d10 = 0.f, d11 = 0.f, d12 = 0.f, d13 = 0.f;

    #pragma unroll 1
    for (int i = 0; i <= TT + 1; ++i) {
        // prefetch xg for layer0 cell
        float x0 = 0.f, x1 = 0.f, x2 = 0.f, x3 = 0.f;
        if (i < TT) {
            const float* xp = xg + ((size_t)i * BB + cm) * GG + blk * 16 + cj;
            x0 = xp[0]; x1 = xp[4]; x2 = xp[8]; x3 = xp[12];
        }

        // ---- stage Hs0 <- h0[i-1] (1<=i<=TT; zero at i==0), Hs1 <- h1[i-3] (i>=3; zero at i==2) ----
        if (i == 0) {
            #pragma unroll
            for (int r = 0; r < 16; ++r) {
                int e = r * 256 + tid;
                int row = e >> 6, sc = e & 63;
                u32 off = row * 1024 + ((u32)(sc ^ (row & 7))) * 16;
                *(uint4*)(smraw + HS0_OFF + off) = make_uint4(0u, 0u, 0u, 0u);
            }
        } else if (i <= TT) {
            const __half* hp0 = h016 + (size_t)(i - 1) * BB * HH;
            #pragma unroll
            for (int r = 0; r < 16; ++r) {
                int e = r * 256 + tid;
                int row = e >> 6, sc = e & 63;
                u32 off = row * 1024 + ((u32)(sc ^ (row & 7))) * 16;
                cp_async16(hs0_base + off, hp0 + (size_t)row * HH + sc * 8);
            }
        }
        if (i == 2) {
            #pragma unroll
            for (int r = 0; r < 16; ++r) {
                int e = r * 256 + tid;
                int row = e >> 6, sc = e & 63;
                u32 off = row * 1024 + ((u32)(sc ^ (row & 7))) * 16;
                *(uint4*)(smraw + HS1_OFF + off) = make_uint4(0u, 0u, 0u, 0u);
            }
        } else if (i >= 3 && i <= TT + 1) {
            const __half* hp1 = h116 + (size_t)(i - 3) * BB * HH;
            #pragma unroll
            for (int r = 0; r < 16; ++r) {
                int e = r * 256 + tid;
                int row = e >> 6, sc = e & 63;
                u32 off = row * 1024 + ((u32)(sc ^ (row & 7))) * 16;
                cp_async16(hs1_base + off, hp1 + (size_t)row * HH + sc * 8);
            }
        }
        cp_commit_wait();
        __syncthreads();

        // ---- body MMA ----
        if (i < TT) {   // layer0: c = Hs0 @ B0^T (pinned B)
            float c00 = 0.f, c01 = 0.f, c02 = 0.f, c03 = 0.f;
            float c10 = 0.f, c11 = 0.f, c12 = 0.f, c13 = 0.f;
            #pragma unroll
            for (int j = 0; j < 16; ++j) {
                int kt = kh2 * 16 + j;
                u32 ch = (u32)((2 * kt + at16) ^ as);
                u32 a0, a1, a2, a3;
                ldsm_x4(a0, a1, a2, a3, a0_lane + ch * 16);
                mma16816(c00, c01, c02, c03, a0, a1, a2, a3, b0f[4 * j], b0f[4 * j + 1]);
                mma16816(c10, c11, c12, c13, a0, a1, a2, a3, b0f[4 * j + 2], b0f[4 * j + 3]);
            }
            *(float2*)&g0p[crow * 20 + cc]           = make_float2(c00, c01);
            *(float2*)&g0p[(crow + 8) * 20 + cc]     = make_float2(c02, c03);
            *(float2*)&g0p[crow * 20 + 8 + cc]       = make_float2(c10, c11);
            *(float2*)&g0p[(crow + 8) * 20 + 8 + cc] = make_float2(c12, c13);
        }
        if (i >= 2) {   // layer1: d += Hs1 @ B1A^T (pinned B; d carries shadow pre-pass)
            #pragma unroll
            for (int j = 0; j < 16; ++j) {
                int kt = kh2 * 16 + j;
                u32 ch = (u32)((2 * kt + at16) ^ as);
                u32 a0, a1, a2, a3;
                ldsm_x4(a0, a1, a2, a3, a1_lane + ch * 16);
                mma16816(d00, d01, d02, d03, a0, a1, a2, a3, b1af[4 * j], b1af[4 * j + 1]);
                mma16816(d10, d11, d12, d13, a0, a1, a2, a3, b1af[4 * j + 2], b1af[4 * j + 3]);
            }
            *(float2*)&g1p[crow * 20 + cc]           = make_float2(d00, d01);
            *(float2*)&g1p[(crow + 8) * 20 + cc]     = make_float2(d02, d03);
            *(float2*)&g1p[crow * 20 + 8 + cc]       = make_float2(d10, d11);
            *(float2*)&g1p[(crow + 8) * 20 + 8 + cc] = make_float2(d12, d13);
        }
        __syncthreads();

        // ---- cells (all 256 threads) ----
        if (i < TT) {
            const float* gp = gates0 + cm * 20 + 4 * cj;
            float4 v0 = *(const float4*)(gp);
            float4 v1 = *(const float4*)(gp + 1280);
            float s0 = v0.x + v1.x, s1 = v0.y + v1.y;
            float s2 = v0.z + v1.z, s3 = v0.w + v1.w;
            float gi_ = sigf (s0 + x0);
            float gf_ = sigf (s1 + x1);
            float gz_ = tanhf(s2 + x2);
            float go_ = sigf (s3 + x3);
            creg0 = gf_ * creg0 + gi_ * gz_;
            float h = go_ * tanhf(creg0);
            h016[((size_t)i * BB + cm) * HH + col] = __float2half(h);
        }
        if (i >= 2) {
            const float* gp = gates1 + cm * 20 + 4 * cj;
            float4 v0 = *(const float4*)(gp);
            float4 v1 = *(const float4*)(gp + 1280);
            float s0 = v0.x + v1.x, s1 = v0.y + v1.y;
            float s2 = v0.z + v1.z, s3 = v0.w + v1.w;
            float gi_ = sigf (s0 + b1g0);
            float gf_ = sigf (s1 + b1g1);
            float gz_ = tanhf(s2 + b1g2);
            float go_ = sigf (s3 + b1g3);
            creg1 = gf_ * creg1 + gi_ * gz_;
            float h = go_ * tanhf(creg1);
            h116[((size_t)(i - 2) * BB + cm) * HH + col] = __float2half(h);
            if (i == TT + 1) finalout[(size_t)cm * HH + col] = h;
        }

        // ---- tail: arrive early, B1B pre-pass in barrier shadow, poll ----
        if (i <= TT) {
            __syncthreads();
            if (tid == 0) red_release_add(cnt, 1u);
            // d = Hs0(h0[i-1]) @ B1B^T  (operand for iter i+1's layer1)
            d00 = 0.f; d01 = 0.f; d02 = 0.f; d03 = 0.f;
            d10 = 0.f; d11 = 0.f; d12 = 0.f; d13 = 0.f;
            if (i >= 1) {
                #pragma unroll
                for (int j = 0; j < 16; ++j) {
                    int kt = kh2 * 16 + j;
                    u32 ch  = (u32)((2 * kt + at16) ^ as);
                    u32 bch = (u32)((2 * kt + btsel) ^ blr);
                    u32 a0, a1, a2, a3, p0, p1, p2, p3;
                    ldsm_x4(a0, a1, a2, a3, a0_lane + ch * 16);
                    ldsm_x4(p0, p1, p2, p3, b1b_lane + bch * 16);
                    mma16816(d00, d01, d02, d03, a0, a1, a2, a3, p0, p1);
                    mma16816(d10, d11, d12, d13, a0, a1, a2, a3, p2, p3);
                }
            }
            if (tid == 0) {
                u32 target = (u32)NBLK * (u32)(i + 1);
                while (ld_acquire(cnt) < target) {}
            }
            __syncthreads();
        }
    }
}

// ---------------- launch ----------------
extern "C" void kernel_launch(void* const* d_in, const int* in_sizes, int n_in,
                              void* d_out, int out_size) {
    const float* x    = (const float*)d_in[0];
    const float* Wih0 = (const float*)d_in[1];
    const float* Whh0 = (const float*)d_in[2];
    const float* bih0 = (const float*)d_in[3];
    const float* bhh0 = (const float*)d_in[4];
    const float* Wih1 = (const float*)d_in[5];
    const float* Whh1 = (const float*)d_in[6];
    const float* bih1 = (const float*)d_in[7];
    const float* bhh1 = (const float*)d_in[8];
    float* out = (float*)d_out;

    float* xg;
    __half *xh, *h016, *h116;
    u32* cnt;
    cudaGetSymbolAddress((void**)&xh,   g_xh);
    cudaGetSymbolAddress((void**)&xg,   g_xg);
    cudaGetSymbolAddress((void**)&h016, g_h016);
    cudaGetSymbolAddress((void**)&h116, g_h116);
    cudaGetSymbolAddress((void**)&cnt,  g_cnt);

    cudaFuncSetAttribute(lstm_fused, cudaFuncAttributeMaxDynamicSharedMemorySize, SMEM_TOTAL);
    cudaFuncSetAttribute(gemm_gates_hmma, cudaFuncAttributeMaxDynamicSharedMemorySize, GSM_TOTAL);

    reset_kernel<<<1, 32>>>();

    dim3 tb(32, 8), tg(TT / 32, FF / 32, BB);
    transpose_x_kernel<<<tg, tb>>>(x);

    gemm_gates_hmma<<<dim3(GG / 64, TT * BB / 128), 256, GSM_TOTAL>>>(xh, Wih0, bih0, bhh0, xg);
    lstm_fused<<<NBLK, 256, SMEM_TOTAL>>>(xg, Whh0, Whh1, Wih1, bih1, bhh1,
                                          h016, h116, out, cnt);
}